// round 14
// baseline (speedup 1.0000x reference)
#include <cuda_runtime.h>
#include <cuda_bf16.h>
#include <cstdint>
#include <cstdio>

// Problem constants
#define BB   8
#define SS   2048
#define DD   1024
#define KK   256
#define NFFT 2048
#define K2   512
#define SH   1024   // folded length
#define HB   4      // batches per chain (2 chains)

// ---------------- device scratch ----------------
__device__ __align__(256) float2        g_tbl[NFFT];              // cos/sin table
__device__ __align__(256) __nv_bfloat16 g_basis1f[K2 * SH];       // rows 0..255 cos(f*s), 256..511 -sin(f*s); col = s-1
__device__ __align__(256) __nv_bfloat16 g_basis2f[2 * SH * KK];   // rows 0..1023 (c/N)cos, rows 1024..2047 -(c/N)sin
__device__ __align__(256) __nv_bfloat16 g_wt[KK * KK];            // WT[j][k] = W[k][j]
__device__ __align__(256) float         g_cwr[KK * DD];           // mag*cos(ph)
__device__ __align__(256) float         g_cwi[KK * DD];           // mag*sin(ph)
__device__ __align__(256) __nv_bfloat16 g_xc[BB * SH * DD];       // x_s + x_{2048-s}
__device__ __align__(256) __nv_bfloat16 g_xd[BB * SH * DD];       // x_s - x_{2048-s}
__device__ __align__(256) float         g_X[BB * K2 * DD];        // Xr rows 0..255, Xi rows 256..511
__device__ __align__(256) __nv_bfloat16 g_xwr[BB * KK * DD];      // Re(x_weighted)
__device__ __align__(256) float         g_dpart[BB * KK * DD];    // xwr - Xr
__device__ __align__(256) __nv_bfloat16 g_delta[BB * K2 * DD];    // [deltar; deltai]
__device__ __align__(256) float         g_ycs[BB * 2 * SH * DD];  // rows 0..1023 ycos, 1024..2047 ysin

// ---------------- helpers ----------------
__device__ __forceinline__ int freq_of(int k) {
    if (k == 255) return 512;
    return (int)((double)k * (512.0 / 255.0));
}
__device__ __forceinline__ uint32_t smem_u32(const void* p) {
    return (uint32_t)__cvta_generic_to_shared(p);
}
__device__ __forceinline__ void cp_async16(void* smem_dst, const void* gmem_src) {
    asm volatile("cp.async.cg.shared.global [%0], [%1], 16;\n"
                 :: "r"(smem_u32(smem_dst)), "l"(gmem_src));
}
__device__ __forceinline__ void cp_commit() {
    asm volatile("cp.async.commit_group;\n");
}
template <int N>
__device__ __forceinline__ void cp_wait() {
    asm volatile("cp.async.wait_group %0;\n" :: "n"(N));
}

// ---------------- precompute ----------------
__global__ void k_tbl() {
    int m = blockIdx.x * blockDim.x + threadIdx.x;
    float ang = (float)m * (6.28318530717958647692f / (float)NFFT);
    float sv, cv;
    sincosf(ang, &sv, &cv);
    g_tbl[m] = make_float2(cv, sv);
}

// merged precompute: basis1f, basis2f, wt, cw
#define N_B1 (K2 * SH)
#define N_B2 (N_B1 + 2 * SH * KK)
#define N_WT (N_B2 + KK * KK)
#define N_CW (N_WT + KK * DD)
__global__ void k_pre(const float* __restrict__ W,
                      const float* __restrict__ mag, const float* __restrict__ ph) {
    int idx = blockIdx.x * blockDim.x + threadIdx.x;
    if (idx < N_B1) {
        int row = idx >> 10;             // 0..511
        int s   = (idx & 1023) + 1;      // 1..1024
        int f   = freq_of(row & 255);
        float2 t = g_tbl[(f * s) & (NFFT - 1)];
        g_basis1f[idx] = __float2bfloat16((row < KK) ? t.x : -t.y);
    } else if (idx < N_B2) {
        int i = idx - N_B1;
        int row = i >> 8;                // 0..2047
        int j   = i & 255;
        int s   = row & 1023;
        int f   = freq_of(j);
        float2 t = g_tbl[(f * s) & (NFFT - 1)];
        float scale = ((f == 0) ? 1.0f : 2.0f) * (1.0f / (float)NFFT);
        g_basis2f[i] = __float2bfloat16((row < SH) ? (scale * t.x) : (-scale * t.y));
    } else if (idx < N_WT) {
        int i = idx - N_B2;
        int j = i >> 8, k = i & 255;
        g_wt[i] = __float2bfloat16(W[k * KK + j]);
    } else if (idx < N_CW) {
        int i = idx - N_WT;
        float sp, cp;
        sincosf(ph[i], &sp, &cp);
        float m = mag[i];
        g_cwr[i] = m * cp;
        g_cwi[i] = m * sp;
    }
}

// ---------------- fold (per-chain, HB batches from b0) ----------------
__global__ void k_fold(const float* __restrict__ x, int b0) {
    int idx = blockIdx.x * blockDim.x + threadIdx.x;
    if (idx >= HB * SH * (DD / 4)) return;
    int b   = (idx >> 18) + b0;          // SH*DD/4 = 2^18 per batch
    int r   = idx & 262143;
    int srow = r >> 8;
    int d4   = (r & 255) << 2;
    int s = srow + 1;
    const float* xb = x + (size_t)b * SS * DD;
    float4 xs = *(const float4*)(xb + (size_t)s * DD + d4);
    float4 c, d;
    if (s == 1024) {
        c = xs;
        d = make_float4(0.f, 0.f, 0.f, 0.f);
    } else {
        float4 xm = *(const float4*)(xb + (size_t)(SS - s) * DD + d4);
        c = make_float4(xs.x + xm.x, xs.y + xm.y, xs.z + xm.z, xs.w + xm.w);
        d = make_float4(xs.x - xm.x, xs.y - xm.y, xs.z - xm.z, xs.w - xm.w);
    }
    size_t o = ((size_t)b * SH + srow) * DD + d4;
    *(__nv_bfloat162*)&g_xc[o]     = __floats2bfloat162_rn(c.x, c.y);
    *(__nv_bfloat162*)&g_xc[o + 2] = __floats2bfloat162_rn(c.z, c.w);
    *(__nv_bfloat162*)&g_xd[o]     = __floats2bfloat162_rn(d.x, d.y);
    *(__nv_bfloat162*)&g_xd[o + 2] = __floats2bfloat162_rn(d.z, d.w);
}

// ---------------- elementwise complex weighting (HB batches, offset b0) ----------------
__global__ void k_elem(int b0) {
    int idx = blockIdx.x * blockDim.x + threadIdx.x;
    if (idx >= HB * KK * DD) return;
    int b = (idx >> 18) + b0;
    int r = idx & 262143;   // k*1024 + d
    size_t xb = (size_t)b * (K2 * DD);
    size_t o1 = ((size_t)b << 18) + r;
    float Xr = g_X[xb + r];
    float Xi = g_X[xb + (KK * DD) + r];
    float cr = g_cwr[r];
    float ci = g_cwi[r];
    float xwr = Xr * cr - Xi * ci;
    float xwi = Xr * ci + Xi * cr;
    g_xwr[o1]   = __float2bfloat16(xwr);
    g_dpart[o1] = xwr - Xr;
    g_delta[xb + (KK * DD) + r] = __float2bfloat16(xwi - Xi);
}

// ---------------- standard GEMM engine, 4-stage, batch-offset ----------------
#define BM 128
#define BN 128
#define BKg 32
#define NSTG 4
#define A_BYTES (BM * 40 * 2)
#define B_BYTES (BKg * 136 * 2)
#define GEMM_SMEM (NSTG * (A_BYTES + B_BYTES))

// MODE 1: bf16 store: aux + 0.1*acc  (interference)
// MODE 3: fp32 store: acc (+ aux_row0[col] if aux && by<bsel)
template <int MODE>
__global__ __launch_bounds__(256, 2) void gemm_mma(
    const __nv_bfloat16* __restrict__ A, int ldA,
    const __nv_bfloat16* __restrict__ B0, const __nv_bfloat16* __restrict__ B1,
    size_t sB, int ldB,
    void* __restrict__ Cv, size_t sC, int ldC,
    const float* __restrict__ aux, size_t sAux,
    int Kdim, int bsel, int b0)
{
    extern __shared__ __align__(16) char dsm[];

    int bz = blockIdx.z + b0;
    int bm = blockIdx.y * BM;
    int bn = blockIdx.x * BN;
    const __nv_bfloat16* Ab = A;
    const __nv_bfloat16* Bb = ((int)blockIdx.y < bsel ? B0 : B1) + sB * bz;

    int tid = threadIdx.x, lane = tid & 31, warp = tid >> 5;
    int wm = (warp & 1) * 64;
    int wn = (warp >> 1) * 32;

    int a_r0 = tid >> 2;
    int a_c  = (tid & 3) << 3;
    int b_r0 = tid >> 4;
    int b_c  = (tid & 15) << 3;

    float acc[4][4][4];
#pragma unroll
    for (int i = 0; i < 4; i++)
#pragma unroll
        for (int j = 0; j < 4; j++)
#pragma unroll
            for (int c = 0; c < 4; c++) acc[i][j][c] = 0.f;

    int nt = Kdim / BKg;

    auto a_base = [&](int st) -> char* { return dsm + st * A_BYTES; };
    auto b_base = [&](int st) -> char* { return dsm + NSTG * A_BYTES + st * B_BYTES; };

    auto load_stage = [&](int s) {
        char* ap = a_base(s & (NSTG - 1));
        char* bp = b_base(s & (NSTG - 1));
        int k0 = s * BKg;
        cp_async16(ap + (a_r0 * 40 + a_c) * 2,        Ab + (size_t)(bm + a_r0) * ldA + k0 + a_c);
        cp_async16(ap + ((a_r0 + 64) * 40 + a_c) * 2, Ab + (size_t)(bm + a_r0 + 64) * ldA + k0 + a_c);
        cp_async16(bp + (b_r0 * 136 + b_c) * 2,        Bb + (size_t)(k0 + b_r0) * ldB + bn + b_c);
        cp_async16(bp + ((b_r0 + 16) * 136 + b_c) * 2, Bb + (size_t)(k0 + b_r0 + 16) * ldB + bn + b_c);
        cp_commit();
    };

#pragma unroll
    for (int i = 0; i < NSTG - 1; i++) load_stage(i);

    for (int kt = 0; kt < nt; kt++) {
        cp_wait<NSTG - 2>();
        __syncthreads();
        if (kt + NSTG - 1 < nt) load_stage(kt + NSTG - 1);
        else                    cp_commit();

        char* ap = a_base(kt & (NSTG - 1));
        char* bp = b_base(kt & (NSTG - 1));

#pragma unroll
        for (int kk = 0; kk < BKg; kk += 16) {
            uint32_t af[4][4], bf[4][2];
            int ar = wm + (lane & 15);
            int ac = kk + ((lane >> 4) << 3);
#pragma unroll
            for (int mi = 0; mi < 4; mi++) {
                uint32_t ad = smem_u32(ap + ((ar + mi * 16) * 40 + ac) * 2);
                asm volatile("ldmatrix.sync.aligned.m8n8.x4.shared.b16 {%0,%1,%2,%3}, [%4];"
                             : "=r"(af[mi][0]), "=r"(af[mi][1]), "=r"(af[mi][2]), "=r"(af[mi][3])
                             : "r"(ad));
            }
            int br = kk + (lane & 15);
#pragma unroll
            for (int ni = 0; ni < 4; ni++) {
                uint32_t bd = smem_u32(bp + (br * 136 + wn + ni * 8) * 2);
                asm volatile("ldmatrix.sync.aligned.m8n8.x2.trans.shared.b16 {%0,%1}, [%2];"
                             : "=r"(bf[ni][0]), "=r"(bf[ni][1]) : "r"(bd));
            }
#pragma unroll
            for (int mi = 0; mi < 4; mi++)
#pragma unroll
                for (int ni = 0; ni < 4; ni++) {
                    float* d = acc[mi][ni];
                    asm volatile(
                        "mma.sync.aligned.m16n8k16.row.col.f32.bf16.bf16.f32 "
                        "{%0,%1,%2,%3}, {%4,%5,%6,%7}, {%8,%9}, {%0,%1,%2,%3};"
                        : "+f"(d[0]), "+f"(d[1]), "+f"(d[2]), "+f"(d[3])
                        : "r"(af[mi][0]), "r"(af[mi][1]), "r"(af[mi][2]), "r"(af[mi][3]),
                          "r"(bf[ni][0]), "r"(bf[ni][1]));
                }
        }
    }

    int g = lane >> 2, t2 = (lane & 3) << 1;
    bool addx = (MODE == 3) && (aux != nullptr) && ((int)blockIdx.y < bsel);
#pragma unroll
    for (int mi = 0; mi < 4; mi++) {
#pragma unroll
        for (int ni = 0; ni < 4; ni++) {
            int row0 = bm + wm + mi * 16 + g;
            int col  = bn + wn + ni * 8 + t2;
            float* d = acc[mi][ni];
            if (MODE == 3) {
                float* C = (float*)Cv + sC * bz;
                float ax0 = 0.f, ax1 = 0.f;
                if (addx) {
                    float2 a = *(const float2*)&aux[sAux * bz + col];
                    ax0 = a.x; ax1 = a.y;
                }
                *(float2*)&C[(size_t)row0 * ldC + col] =
                    make_float2(d[0] + ax0, d[1] + ax1);
                *(float2*)&C[(size_t)(row0 + 8) * ldC + col] =
                    make_float2(d[2] + ax0, d[3] + ax1);
            } else {
                __nv_bfloat16* C = (__nv_bfloat16*)Cv + sC * bz;
                const float* ax = aux + sAux * bz;
                float2 a0 = *(const float2*)&ax[(size_t)row0 * ldC + col];
                float2 a1 = *(const float2*)&ax[(size_t)(row0 + 8) * ldC + col];
                *(__nv_bfloat162*)&C[(size_t)row0 * ldC + col] =
                    __floats2bfloat162_rn(a0.x + 0.1f * d[0], a0.y + 0.1f * d[1]);
                *(__nv_bfloat162*)&C[(size_t)(row0 + 8) * ldC + col] =
                    __floats2bfloat162_rn(a1.x + 0.1f * d[2], a1.y + 0.1f * d[3]);
            }
        }
    }
}

// ---------------- combine (mirror + residual + row1024) + LayerNorm ----------------
// blockIdx.x = rp in 0..1024, blockIdx.y = local batch (+b0). 256 threads.
__global__ __launch_bounds__(256) void k_combine(
    const float* __restrict__ x, float* __restrict__ out,
    const float* __restrict__ gamma, const float* __restrict__ beta, int b0)
{
    __shared__ float r1[8], r2[8];
    int b = blockIdx.y + b0, rp = blockIdx.x, t = threadIdx.x;
    int w = t >> 5, l = t & 31;
    int d4 = t << 2;
    const float* xb = x + (size_t)b * SS * DD;
    const float* ycs = g_ycs + (size_t)b * 2 * SH * DD;
    float4 gmv = ((const float4*)gamma)[t];
    float4 btv = ((const float4*)beta)[t];

    float4 vc, vs, va;
    if (rp < SH) {
        vc = *(const float4*)(ycs + (size_t)rp * DD + d4);
        vs = *(const float4*)(ycs + (size_t)(SH + rp) * DD + d4);
        float4 xv = *(const float4*)(xb + (size_t)rp * DD + d4);
        va = make_float4(vc.x + vs.x + 2.f * xv.x, vc.y + vs.y + 2.f * xv.y,
                         vc.z + vs.z + 2.f * xv.z, vc.w + vs.w + 2.f * xv.w);
    } else {
        // rp == 1024: ycos_1024[d] = sum_k (c/N)(-1)^f deltar[k][d]
        float a0 = 0.f, a1 = 0.f, a2 = 0.f, a3 = 0.f;
        const __nv_bfloat16* dr = g_delta + (size_t)b * K2 * DD;
        for (int k = 0; k < KK; k++) {
            int f = freq_of(k);
            float wgt = ((f == 0) ? 1.0f : 2.0f) * (1.0f / (float)NFFT);
            if (f & 1) wgt = -wgt;
            __nv_bfloat162 p0 = *(const __nv_bfloat162*)(dr + (size_t)k * DD + d4);
            __nv_bfloat162 p1 = *(const __nv_bfloat162*)(dr + (size_t)k * DD + d4 + 2);
            a0 += wgt * __bfloat162float(p0.x);
            a1 += wgt * __bfloat162float(p0.y);
            a2 += wgt * __bfloat162float(p1.x);
            a3 += wgt * __bfloat162float(p1.y);
        }
        float4 xv = *(const float4*)(xb + (size_t)SH * DD + d4);
        va = make_float4(a0 + 2.f * xv.x, a1 + 2.f * xv.y,
                         a2 + 2.f * xv.z, a3 + 2.f * xv.w);
    }

    // --- LN row A ---
    {
        float s1 = va.x + va.y + va.z + va.w;
        float s2 = va.x * va.x + va.y * va.y + va.z * va.z + va.w * va.w;
#pragma unroll
        for (int o = 16; o > 0; o >>= 1) {
            s1 += __shfl_down_sync(0xffffffffu, s1, o);
            s2 += __shfl_down_sync(0xffffffffu, s2, o);
        }
        if (l == 0) { r1[w] = s1; r2[w] = s2; }
        __syncthreads();
        float mu = 0.f, m2 = 0.f;
#pragma unroll
        for (int i = 0; i < 8; i++) { mu += r1[i]; m2 += r2[i]; }
        mu *= (1.0f / (float)DD);
        float var = m2 * (1.0f / (float)DD) - mu * mu;
        float rs = rsqrtf(var + 1e-5f);
        float* op = out + ((size_t)b * SS + rp) * DD + d4;
        op[0] = (va.x - mu) * rs * gmv.x + btv.x;
        op[1] = (va.y - mu) * rs * gmv.y + btv.y;
        op[2] = (va.z - mu) * rs * gmv.z + btv.z;
        op[3] = (va.w - mu) * rs * gmv.w + btv.w;
    }

    // --- row B: mirror 2048-rp, rp in 1..1023 ---
    if (rp >= 1 && rp < SH) {
        float4 xv = *(const float4*)(xb + (size_t)(SS - rp) * DD + d4);
        float4 vb = make_float4(vc.x - vs.x + 2.f * xv.x, vc.y - vs.y + 2.f * xv.y,
                                vc.z - vs.z + 2.f * xv.z, vc.w - vs.w + 2.f * xv.w);
        float s1 = vb.x + vb.y + vb.z + vb.w;
        float s2 = vb.x * vb.x + vb.y * vb.y + vb.z * vb.z + vb.w * vb.w;
#pragma unroll
        for (int o = 16; o > 0; o >>= 1) {
            s1 += __shfl_down_sync(0xffffffffu, s1, o);
            s2 += __shfl_down_sync(0xffffffffu, s2, o);
        }
        __syncthreads();   // protect r1/r2 reuse
        if (l == 0) { r1[w] = s1; r2[w] = s2; }
        __syncthreads();
        float mu = 0.f, m2 = 0.f;
#pragma unroll
        for (int i = 0; i < 8; i++) { mu += r1[i]; m2 += r2[i]; }
        mu *= (1.0f / (float)DD);
        float var = m2 * (1.0f / (float)DD) - mu * mu;
        float rs = rsqrtf(var + 1e-5f);
        float* op = out + ((size_t)b * SS + (SS - rp)) * DD + d4;
        op[0] = (vb.x - mu) * rs * gmv.x + btv.x;
        op[1] = (vb.y - mu) * rs * gmv.y + btv.y;
        op[2] = (vb.z - mu) * rs * gmv.z + btv.z;
        op[3] = (vb.w - mu) * rs * gmv.w + btv.w;
    }
}

// ---------------- launch ----------------
extern "C" void kernel_launch(void* const* d_in, const int* in_sizes, int n_in,
                              void* d_out, int out_size) {
    const float* x     = (const float*)d_in[0];
    const float* mag   = (const float*)d_in[1];
    const float* ph    = (const float*)d_in[2];
    const float* W     = (const float*)d_in[3];
    const float* gamma = (const float*)d_in[4];
    const float* beta  = (const float*)d_in[5];
    float* out = (float*)d_out;

    void *p_b1, *p_b2, *p_wt, *p_xc, *p_xd, *p_X, *p_xwr, *p_dp, *p_dl, *p_ycs;
    cudaGetSymbolAddress(&p_b1, g_basis1f);
    cudaGetSymbolAddress(&p_b2, g_basis2f);
    cudaGetSymbolAddress(&p_wt, g_wt);
    cudaGetSymbolAddress(&p_xc, g_xc);
    cudaGetSymbolAddress(&p_xd, g_xd);
    cudaGetSymbolAddress(&p_X, g_X);
    cudaGetSymbolAddress(&p_xwr, g_xwr);
    cudaGetSymbolAddress(&p_dp, g_dpart);
    cudaGetSymbolAddress(&p_dl, g_delta);
    cudaGetSymbolAddress(&p_ycs, g_ycs);

    cudaFuncSetAttribute(gemm_mma<1>, cudaFuncAttributeMaxDynamicSharedMemorySize, GEMM_SMEM);
    cudaFuncSetAttribute(gemm_mma<3>, cudaFuncAttributeMaxDynamicSharedMemorySize, GEMM_SMEM);

    // one-time resources (created during the uncaptured correctness call)
    // Same footprint as R11/R13 (2 extra streams) which passed graph teardown.
    static cudaStream_t sA = [] { cudaStream_t s; cudaStreamCreateWithFlags(&s, cudaStreamNonBlocking); return s; }();
    static cudaStream_t sB = [] { cudaStream_t s; cudaStreamCreateWithFlags(&s, cudaStreamNonBlocking); return s; }();
    static cudaEvent_t eFork = [] { cudaEvent_t e; cudaEventCreateWithFlags(&e, cudaEventDisableTiming); return e; }();
    static cudaEvent_t ePre  = [] { cudaEvent_t e; cudaEventCreateWithFlags(&e, cudaEventDisableTiming); return e; }();
    static cudaEvent_t eAend = [] { cudaEvent_t e; cudaEventCreateWithFlags(&e, cudaEventDisableTiming); return e; }();
    static cudaEvent_t eBend = [] { cudaEvent_t e; cudaEventCreateWithFlags(&e, cudaEventDisableTiming); return e; }();

    cudaStream_t s0 = 0;   // legacy capture stream — NO kernels here (implicit-sync trap)

    // ---- fork ----
    cudaEventRecord(eFork, s0);
    cudaStreamWaitEvent(sA, eFork, 0);
    cudaStreamWaitEvent(sB, eFork, 0);

    // ---- chain A (sA): precompute + fold(0) + pipeline(b0=0) ----
    k_tbl<<<NFFT / 256, 256, 0, sA>>>();
    k_pre<<<(N_CW + 255) / 256, 256, 0, sA>>>(W, mag, ph);
    cudaEventRecord(ePre, sA);
    k_fold<<<(HB * SH * (DD / 4)) / 256, 256, 0, sA>>>(x, 0);

    // ---- chain B (sB): fold(4) overlaps precompute; wait ePre before GEMMs ----
    k_fold<<<(HB * SH * (DD / 4)) / 256, 256, 0, sB>>>(x, HB);
    cudaStreamWaitEvent(sB, ePre, 0);

    struct { cudaStream_t st; int b0; } chains[2] = { { sA, 0 }, { sB, HB } };
    for (int c = 0; c < 2; c++) {
        cudaStream_t st = chains[c].st;
        int b0 = chains[c].b0;

        // G1 (folded): X[b] = basis1f @ {xc|xd}[b], +x0 on cos tiles
        gemm_mma<3><<<dim3(DD / BN, K2 / BM, HB), 256, GEMM_SMEM, st>>>(
            (const __nv_bfloat16*)p_b1, SH,
            (const __nv_bfloat16*)p_xc, (const __nv_bfloat16*)p_xd, (size_t)SH * DD, DD,
            p_X, (size_t)K2 * DD, DD,
            x, (size_t)SS * DD,
            SH, /*bsel=*/2, b0);

        // elementwise complex weighting
        k_elem<<<(HB * KK * DD) / 256, 256, 0, st>>>(b0);

        // interference: deltar[b] = dpart + 0.1 * (WT @ xwr[b])
        gemm_mma<1><<<dim3(DD / BN, KK / BM, HB), 256, GEMM_SMEM, st>>>(
            (const __nv_bfloat16*)p_wt, KK,
            (const __nv_bfloat16*)p_xwr, (const __nv_bfloat16*)p_xwr, (size_t)KK * DD, DD,
            p_dl, (size_t)K2 * DD, DD,
            (const float*)p_dp, (size_t)KK * DD,
            KK, /*bsel=*/8, b0);

        // G2 (folded): ycs[b] = basis2f @ {deltar|deltai}[b]
        gemm_mma<3><<<dim3(DD / BN, (2 * SH) / BM, HB), 256, GEMM_SMEM, st>>>(
            (const __nv_bfloat16*)p_b2, KK,
            (const __nv_bfloat16*)p_dl, (const __nv_bfloat16*)p_dl + (size_t)KK * DD,
            (size_t)K2 * DD, DD,
            p_ycs, (size_t)2 * SH * DD, DD,
            nullptr, 0,
            KK, /*bsel=*/8, b0);

        // combine: mirror + residual + row1024 + LayerNorm
        k_combine<<<dim3(SH + 1, HB), 256, 0, st>>>(x, out, gamma, beta, b0);
    }

    // ---- join both chains back into the capture stream ----
    cudaEventRecord(eAend, sA);
    cudaEventRecord(eBend, sB);
    cudaStreamWaitEvent(s0, eAend, 0);
    cudaStreamWaitEvent(s0, eBend, 0);
}

// round 15
// speedup vs baseline: 1.0316x; 1.0316x over previous
#include <cuda_runtime.h>
#include <cuda_bf16.h>
#include <cstdint>
#include <cstdio>

// Problem constants
#define BB   8
#define SS   2048
#define DD   1024
#define KK   256
#define NFFT 2048
#define K2   512
#define SH   1024   // folded length
#define HB   4      // batches per chain (2 chains)

// ---------------- device scratch ----------------
__device__ __align__(256) float2        g_tbl[NFFT];              // cos/sin table
__device__ __align__(256) __nv_bfloat16 g_basis1f[K2 * SH];       // rows 0..255 cos(f*s), 256..511 -sin(f*s); col = s-1
__device__ __align__(256) __nv_bfloat16 g_basis2f[2 * SH * KK];   // rows 0..1023 (c/N)cos, rows 1024..2047 -(c/N)sin
__device__ __align__(256) __nv_bfloat16 g_wt[KK * KK];            // WT[j][k] = W[k][j]
__device__ __align__(256) float         g_cwr[KK * DD];           // mag*cos(ph)
__device__ __align__(256) float         g_cwi[KK * DD];           // mag*sin(ph)
__device__ __align__(256) __nv_bfloat16 g_xc[BB * SH * DD];       // x_s + x_{2048-s}
__device__ __align__(256) __nv_bfloat16 g_xd[BB * SH * DD];       // x_s - x_{2048-s}
__device__ __align__(256) float         g_X[BB * K2 * DD];        // Xr rows 0..255, Xi rows 256..511
__device__ __align__(256) __nv_bfloat16 g_xwr[BB * KK * DD];      // Re(x_weighted)
__device__ __align__(256) float         g_dpart[BB * KK * DD];    // xwr - Xr
__device__ __align__(256) __nv_bfloat16 g_delta[BB * K2 * DD];    // [deltar; deltai]
__device__ __align__(256) __nv_bfloat16 g_ycs[BB * 2 * SH * DD];  // bf16: rows 0..1023 ycos, 1024..2047 ysin

// ---------------- helpers ----------------
__device__ __forceinline__ int freq_of(int k) {
    if (k == 255) return 512;
    return (int)((double)k * (512.0 / 255.0));
}
__device__ __forceinline__ uint32_t smem_u32(const void* p) {
    return (uint32_t)__cvta_generic_to_shared(p);
}
__device__ __forceinline__ void cp_async16(void* smem_dst, const void* gmem_src) {
    asm volatile("cp.async.cg.shared.global [%0], [%1], 16;\n"
                 :: "r"(smem_u32(smem_dst)), "l"(gmem_src));
}
__device__ __forceinline__ void cp_commit() {
    asm volatile("cp.async.commit_group;\n");
}
template <int N>
__device__ __forceinline__ void cp_wait() {
    asm volatile("cp.async.wait_group %0;\n" :: "n"(N));
}

// ---------------- precompute ----------------
__global__ void k_tbl() {
    int m = blockIdx.x * blockDim.x + threadIdx.x;
    float ang = (float)m * (6.28318530717958647692f / (float)NFFT);
    float sv, cv;
    sincosf(ang, &sv, &cv);
    g_tbl[m] = make_float2(cv, sv);
}

// merged precompute: basis1f, basis2f, wt, cw
#define N_B1 (K2 * SH)
#define N_B2 (N_B1 + 2 * SH * KK)
#define N_WT (N_B2 + KK * KK)
#define N_CW (N_WT + KK * DD)
__global__ void k_pre(const float* __restrict__ W,
                      const float* __restrict__ mag, const float* __restrict__ ph) {
    int idx = blockIdx.x * blockDim.x + threadIdx.x;
    if (idx < N_B1) {
        int row = idx >> 10;             // 0..511
        int s   = (idx & 1023) + 1;      // 1..1024
        int f   = freq_of(row & 255);
        float2 t = g_tbl[(f * s) & (NFFT - 1)];
        g_basis1f[idx] = __float2bfloat16((row < KK) ? t.x : -t.y);
    } else if (idx < N_B2) {
        int i = idx - N_B1;
        int row = i >> 8;                // 0..2047
        int j   = i & 255;
        int s   = row & 1023;
        int f   = freq_of(j);
        float2 t = g_tbl[(f * s) & (NFFT - 1)];
        float scale = ((f == 0) ? 1.0f : 2.0f) * (1.0f / (float)NFFT);
        g_basis2f[i] = __float2bfloat16((row < SH) ? (scale * t.x) : (-scale * t.y));
    } else if (idx < N_WT) {
        int i = idx - N_B2;
        int j = i >> 8, k = i & 255;
        g_wt[i] = __float2bfloat16(W[k * KK + j]);
    } else if (idx < N_CW) {
        int i = idx - N_WT;
        float sp, cp;
        sincosf(ph[i], &sp, &cp);
        float m = mag[i];
        g_cwr[i] = m * cp;
        g_cwi[i] = m * sp;
    }
}

// ---------------- fold (all batches) ----------------
__global__ void k_fold(const float* __restrict__ x) {
    int idx = blockIdx.x * blockDim.x + threadIdx.x;
    if (idx >= BB * SH * (DD / 4)) return;
    int b   = idx >> 18;
    int r   = idx & 262143;
    int srow = r >> 8;
    int d4   = (r & 255) << 2;
    int s = srow + 1;
    const float* xb = x + (size_t)b * SS * DD;
    float4 xs = *(const float4*)(xb + (size_t)s * DD + d4);
    float4 c, d;
    if (s == 1024) {
        c = xs;
        d = make_float4(0.f, 0.f, 0.f, 0.f);
    } else {
        float4 xm = *(const float4*)(xb + (size_t)(SS - s) * DD + d4);
        c = make_float4(xs.x + xm.x, xs.y + xm.y, xs.z + xm.z, xs.w + xm.w);
        d = make_float4(xs.x - xm.x, xs.y - xm.y, xs.z - xm.z, xs.w - xm.w);
    }
    size_t o = ((size_t)b * SH + srow) * DD + d4;
    *(__nv_bfloat162*)&g_xc[o]     = __floats2bfloat162_rn(c.x, c.y);
    *(__nv_bfloat162*)&g_xc[o + 2] = __floats2bfloat162_rn(c.z, c.w);
    *(__nv_bfloat162*)&g_xd[o]     = __floats2bfloat162_rn(d.x, d.y);
    *(__nv_bfloat162*)&g_xd[o + 2] = __floats2bfloat162_rn(d.z, d.w);
}

// ---------------- elementwise complex weighting (HB batches, offset b0) ----------------
__global__ void k_elem(int b0) {
    int idx = blockIdx.x * blockDim.x + threadIdx.x;
    if (idx >= HB * KK * DD) return;
    int b = (idx >> 18) + b0;
    int r = idx & 262143;   // k*1024 + d
    size_t xb = (size_t)b * (K2 * DD);
    size_t o1 = ((size_t)b << 18) + r;
    float Xr = g_X[xb + r];
    float Xi = g_X[xb + (KK * DD) + r];
    float cr = g_cwr[r];
    float ci = g_cwi[r];
    float xwr = Xr * cr - Xi * ci;
    float xwi = Xr * ci + Xi * cr;
    g_xwr[o1]   = __float2bfloat16(xwr);
    g_dpart[o1] = xwr - Xr;
    g_delta[xb + (KK * DD) + r] = __float2bfloat16(xwi - Xi);
}

// ---------------- standard GEMM engine, 4-stage, batch-offset ----------------
#define BM 128
#define BN 128
#define BKg 32
#define NSTG 4
#define A_BYTES (BM * 40 * 2)
#define B_BYTES (BKg * 136 * 2)
#define GEMM_SMEM (NSTG * (A_BYTES + B_BYTES))

// MODE 1: bf16 store: aux + 0.1*acc  (interference)
// MODE 3: fp32 store: acc (+ aux_row0[col] if aux && by<bsel)
// MODE 4: bf16 store: acc            (G2 -> ycs)
template <int MODE>
__global__ __launch_bounds__(256, 2) void gemm_mma(
    const __nv_bfloat16* __restrict__ A, int ldA,
    const __nv_bfloat16* __restrict__ B0, const __nv_bfloat16* __restrict__ B1,
    size_t sB, int ldB,
    void* __restrict__ Cv, size_t sC, int ldC,
    const float* __restrict__ aux, size_t sAux,
    int Kdim, int bsel, int b0)
{
    extern __shared__ __align__(16) char dsm[];

    int bz = blockIdx.z + b0;
    int bm = blockIdx.y * BM;
    int bn = blockIdx.x * BN;
    const __nv_bfloat16* Ab = A;
    const __nv_bfloat16* Bb = ((int)blockIdx.y < bsel ? B0 : B1) + sB * bz;

    int tid = threadIdx.x, lane = tid & 31, warp = tid >> 5;
    int wm = (warp & 1) * 64;
    int wn = (warp >> 1) * 32;

    int a_r0 = tid >> 2;
    int a_c  = (tid & 3) << 3;
    int b_r0 = tid >> 4;
    int b_c  = (tid & 15) << 3;

    float acc[4][4][4];
#pragma unroll
    for (int i = 0; i < 4; i++)
#pragma unroll
        for (int j = 0; j < 4; j++)
#pragma unroll
            for (int c = 0; c < 4; c++) acc[i][j][c] = 0.f;

    int nt = Kdim / BKg;

    auto a_base = [&](int st) -> char* { return dsm + st * A_BYTES; };
    auto b_base = [&](int st) -> char* { return dsm + NSTG * A_BYTES + st * B_BYTES; };

    auto load_stage = [&](int s) {
        char* ap = a_base(s & (NSTG - 1));
        char* bp = b_base(s & (NSTG - 1));
        int k0 = s * BKg;
        cp_async16(ap + (a_r0 * 40 + a_c) * 2,        Ab + (size_t)(bm + a_r0) * ldA + k0 + a_c);
        cp_async16(ap + ((a_r0 + 64) * 40 + a_c) * 2, Ab + (size_t)(bm + a_r0 + 64) * ldA + k0 + a_c);
        cp_async16(bp + (b_r0 * 136 + b_c) * 2,        Bb + (size_t)(k0 + b_r0) * ldB + bn + b_c);
        cp_async16(bp + ((b_r0 + 16) * 136 + b_c) * 2, Bb + (size_t)(k0 + b_r0 + 16) * ldB + bn + b_c);
        cp_commit();
    };

#pragma unroll
    for (int i = 0; i < NSTG - 1; i++) load_stage(i);

    for (int kt = 0; kt < nt; kt++) {
        cp_wait<NSTG - 2>();
        __syncthreads();
        if (kt + NSTG - 1 < nt) load_stage(kt + NSTG - 1);
        else                    cp_commit();

        char* ap = a_base(kt & (NSTG - 1));
        char* bp = b_base(kt & (NSTG - 1));

#pragma unroll
        for (int kk = 0; kk < BKg; kk += 16) {
            uint32_t af[4][4], bf[4][2];
            int ar = wm + (lane & 15);
            int ac = kk + ((lane >> 4) << 3);
#pragma unroll
            for (int mi = 0; mi < 4; mi++) {
                uint32_t ad = smem_u32(ap + ((ar + mi * 16) * 40 + ac) * 2);
                asm volatile("ldmatrix.sync.aligned.m8n8.x4.shared.b16 {%0,%1,%2,%3}, [%4];"
                             : "=r"(af[mi][0]), "=r"(af[mi][1]), "=r"(af[mi][2]), "=r"(af[mi][3])
                             : "r"(ad));
            }
            int br = kk + (lane & 15);
#pragma unroll
            for (int ni = 0; ni < 4; ni++) {
                uint32_t bd = smem_u32(bp + (br * 136 + wn + ni * 8) * 2);
                asm volatile("ldmatrix.sync.aligned.m8n8.x2.trans.shared.b16 {%0,%1}, [%2];"
                             : "=r"(bf[ni][0]), "=r"(bf[ni][1]) : "r"(bd));
            }
#pragma unroll
            for (int mi = 0; mi < 4; mi++)
#pragma unroll
                for (int ni = 0; ni < 4; ni++) {
                    float* d = acc[mi][ni];
                    asm volatile(
                        "mma.sync.aligned.m16n8k16.row.col.f32.bf16.bf16.f32 "
                        "{%0,%1,%2,%3}, {%4,%5,%6,%7}, {%8,%9}, {%0,%1,%2,%3};"
                        : "+f"(d[0]), "+f"(d[1]), "+f"(d[2]), "+f"(d[3])
                        : "r"(af[mi][0]), "r"(af[mi][1]), "r"(af[mi][2]), "r"(af[mi][3]),
                          "r"(bf[ni][0]), "r"(bf[ni][1]));
                }
        }
    }

    int g = lane >> 2, t2 = (lane & 3) << 1;
    bool addx = (MODE == 3) && (aux != nullptr) && ((int)blockIdx.y < bsel);
#pragma unroll
    for (int mi = 0; mi < 4; mi++) {
#pragma unroll
        for (int ni = 0; ni < 4; ni++) {
            int row0 = bm + wm + mi * 16 + g;
            int col  = bn + wn + ni * 8 + t2;
            float* d = acc[mi][ni];
            if (MODE == 3) {
                float* C = (float*)Cv + sC * bz;
                float ax0 = 0.f, ax1 = 0.f;
                if (addx) {
                    float2 a = *(const float2*)&aux[sAux * bz + col];
                    ax0 = a.x; ax1 = a.y;
                }
                *(float2*)&C[(size_t)row0 * ldC + col] =
                    make_float2(d[0] + ax0, d[1] + ax1);
                *(float2*)&C[(size_t)(row0 + 8) * ldC + col] =
                    make_float2(d[2] + ax0, d[3] + ax1);
            } else if (MODE == 4) {
                __nv_bfloat16* C = (__nv_bfloat16*)Cv + sC * bz;
                *(__nv_bfloat162*)&C[(size_t)row0 * ldC + col] =
                    __floats2bfloat162_rn(d[0], d[1]);
                *(__nv_bfloat162*)&C[(size_t)(row0 + 8) * ldC + col] =
                    __floats2bfloat162_rn(d[2], d[3]);
            } else {
                __nv_bfloat16* C = (__nv_bfloat16*)Cv + sC * bz;
                const float* ax = aux + sAux * bz;
                float2 a0 = *(const float2*)&ax[(size_t)row0 * ldC + col];
                float2 a1 = *(const float2*)&ax[(size_t)(row0 + 8) * ldC + col];
                *(__nv_bfloat162*)&C[(size_t)row0 * ldC + col] =
                    __floats2bfloat162_rn(a0.x + 0.1f * d[0], a0.y + 0.1f * d[1]);
                *(__nv_bfloat162*)&C[(size_t)(row0 + 8) * ldC + col] =
                    __floats2bfloat162_rn(a1.x + 0.1f * d[2], a1.y + 0.1f * d[3]);
            }
        }
    }
}

// ---------------- combine (mirror + residual + row1024) + LayerNorm ----------------
// blockIdx.x = rp in 0..1024, blockIdx.y = local batch (+b0). 256 threads.
// Single fused reduction for both rows (one barrier).
__global__ __launch_bounds__(256) void k_combine(
    const float* __restrict__ x, float* __restrict__ out,
    const float* __restrict__ gamma, const float* __restrict__ beta, int b0)
{
    __shared__ float4 red[8];
    int b = blockIdx.y + b0, rp = blockIdx.x, t = threadIdx.x;
    int w = t >> 5, l = t & 31;
    int d4 = t << 2;
    const float* xb = x + (size_t)b * SS * DD;
    const __nv_bfloat16* ycs = g_ycs + (size_t)b * 2 * SH * DD;
    float4 gmv = ((const float4*)gamma)[t];
    float4 btv = ((const float4*)beta)[t];

    bool hasB = (rp >= 1 && rp < SH);
    float4 va, vb = make_float4(0.f, 0.f, 0.f, 0.f);

    if (rp < SH) {
        __nv_bfloat162 c0 = *(const __nv_bfloat162*)(ycs + (size_t)rp * DD + d4);
        __nv_bfloat162 c1 = *(const __nv_bfloat162*)(ycs + (size_t)rp * DD + d4 + 2);
        __nv_bfloat162 s0 = *(const __nv_bfloat162*)(ycs + (size_t)(SH + rp) * DD + d4);
        __nv_bfloat162 s1 = *(const __nv_bfloat162*)(ycs + (size_t)(SH + rp) * DD + d4 + 2);
        float vc0 = __bfloat162float(c0.x), vc1 = __bfloat162float(c0.y);
        float vc2 = __bfloat162float(c1.x), vc3 = __bfloat162float(c1.y);
        float vs0 = __bfloat162float(s0.x), vs1 = __bfloat162float(s0.y);
        float vs2 = __bfloat162float(s1.x), vs3 = __bfloat162float(s1.y);
        float4 xv = *(const float4*)(xb + (size_t)rp * DD + d4);
        va = make_float4(vc0 + vs0 + 2.f * xv.x, vc1 + vs1 + 2.f * xv.y,
                         vc2 + vs2 + 2.f * xv.z, vc3 + vs3 + 2.f * xv.w);
        if (hasB) {
            float4 xm = *(const float4*)(xb + (size_t)(SS - rp) * DD + d4);
            vb = make_float4(vc0 - vs0 + 2.f * xm.x, vc1 - vs1 + 2.f * xm.y,
                             vc2 - vs2 + 2.f * xm.z, vc3 - vs3 + 2.f * xm.w);
        }
    } else {
        // rp == 1024: ycos_1024[d] = sum_k (c/N)(-1)^f deltar[k][d]
        float a0 = 0.f, a1 = 0.f, a2 = 0.f, a3 = 0.f;
        const __nv_bfloat16* dr = g_delta + (size_t)b * K2 * DD;
        for (int k = 0; k < KK; k++) {
            int f = freq_of(k);
            float wgt = ((f == 0) ? 1.0f : 2.0f) * (1.0f / (float)NFFT);
            if (f & 1) wgt = -wgt;
            __nv_bfloat162 p0 = *(const __nv_bfloat162*)(dr + (size_t)k * DD + d4);
            __nv_bfloat162 p1 = *(const __nv_bfloat162*)(dr + (size_t)k * DD + d4 + 2);
            a0 += wgt * __bfloat162float(p0.x);
            a1 += wgt * __bfloat162float(p0.y);
            a2 += wgt * __bfloat162float(p1.x);
            a3 += wgt * __bfloat162float(p1.y);
        }
        float4 xv = *(const float4*)(xb + (size_t)SH * DD + d4);
        va = make_float4(a0 + 2.f * xv.x, a1 + 2.f * xv.y,
                         a2 + 2.f * xv.z, a3 + 2.f * xv.w);
    }

    // fused reduction: (sumA, sumsqA, sumB, sumsqB) in one tree + one barrier
    float s1a = va.x + va.y + va.z + va.w;
    float s2a = va.x * va.x + va.y * va.y + va.z * va.z + va.w * va.w;
    float s1b = vb.x + vb.y + vb.z + vb.w;
    float s2b = vb.x * vb.x + vb.y * vb.y + vb.z * vb.z + vb.w * vb.w;
#pragma unroll
    for (int o = 16; o > 0; o >>= 1) {
        s1a += __shfl_down_sync(0xffffffffu, s1a, o);
        s2a += __shfl_down_sync(0xffffffffu, s2a, o);
        s1b += __shfl_down_sync(0xffffffffu, s1b, o);
        s2b += __shfl_down_sync(0xffffffffu, s2b, o);
    }
    if (l == 0) red[w] = make_float4(s1a, s2a, s1b, s2b);
    __syncthreads();
    float muA = 0.f, m2A = 0.f, muB = 0.f, m2B = 0.f;
#pragma unroll
    for (int i = 0; i < 8; i++) {
        float4 rr = red[i];
        muA += rr.x; m2A += rr.y; muB += rr.z; m2B += rr.w;
    }
    muA *= (1.0f / (float)DD);
    float varA = m2A * (1.0f / (float)DD) - muA * muA;
    float rsA = rsqrtf(varA + 1e-5f);
    {
        float* op = out + ((size_t)b * SS + rp) * DD + d4;
        op[0] = (va.x - muA) * rsA * gmv.x + btv.x;
        op[1] = (va.y - muA) * rsA * gmv.y + btv.y;
        op[2] = (va.z - muA) * rsA * gmv.z + btv.z;
        op[3] = (va.w - muA) * rsA * gmv.w + btv.w;
    }
    if (hasB) {
        muB *= (1.0f / (float)DD);
        float varB = m2B * (1.0f / (float)DD) - muB * muB;
        float rsB = rsqrtf(varB + 1e-5f);
        float* op = out + ((size_t)b * SS + (SS - rp)) * DD + d4;
        op[0] = (vb.x - muB) * rsB * gmv.x + btv.x;
        op[1] = (vb.y - muB) * rsB * gmv.y + btv.y;
        op[2] = (vb.z - muB) * rsB * gmv.z + btv.z;
        op[3] = (vb.w - muB) * rsB * gmv.w + btv.w;
    }
}

// ---------------- launch (R11 topology: chain A on s0, chain B on sB, pre on sPre) ----
extern "C" void kernel_launch(void* const* d_in, const int* in_sizes, int n_in,
                              void* d_out, int out_size) {
    const float* x     = (const float*)d_in[0];
    const float* mag   = (const float*)d_in[1];
    const float* ph    = (const float*)d_in[2];
    const float* W     = (const float*)d_in[3];
    const float* gamma = (const float*)d_in[4];
    const float* beta  = (const float*)d_in[5];
    float* out = (float*)d_out;

    void *p_b1, *p_b2, *p_wt, *p_xc, *p_xd, *p_X, *p_xwr, *p_dp, *p_dl, *p_ycs;
    cudaGetSymbolAddress(&p_b1, g_basis1f);
    cudaGetSymbolAddress(&p_b2, g_basis2f);
    cudaGetSymbolAddress(&p_wt, g_wt);
    cudaGetSymbolAddress(&p_xc, g_xc);
    cudaGetSymbolAddress(&p_xd, g_xd);
    cudaGetSymbolAddress(&p_X, g_X);
    cudaGetSymbolAddress(&p_xwr, g_xwr);
    cudaGetSymbolAddress(&p_dp, g_dpart);
    cudaGetSymbolAddress(&p_dl, g_delta);
    cudaGetSymbolAddress(&p_ycs, g_ycs);

    cudaFuncSetAttribute(gemm_mma<1>, cudaFuncAttributeMaxDynamicSharedMemorySize, GEMM_SMEM);
    cudaFuncSetAttribute(gemm_mma<3>, cudaFuncAttributeMaxDynamicSharedMemorySize, GEMM_SMEM);
    cudaFuncSetAttribute(gemm_mma<4>, cudaFuncAttributeMaxDynamicSharedMemorySize, GEMM_SMEM);

    // one-time resources (created during the uncaptured correctness call)
    static cudaStream_t sPre = [] { cudaStream_t s; cudaStreamCreateWithFlags(&s, cudaStreamNonBlocking); return s; }();
    static cudaStream_t sB   = [] { cudaStream_t s; cudaStreamCreateWithFlags(&s, cudaStreamNonBlocking); return s; }();
    static cudaEvent_t eFork = [] { cudaEvent_t e; cudaEventCreateWithFlags(&e, cudaEventDisableTiming); return e; }();
    static cudaEvent_t ePre  = [] { cudaEvent_t e; cudaEventCreateWithFlags(&e, cudaEventDisableTiming); return e; }();
    static cudaEvent_t eMid  = [] { cudaEvent_t e; cudaEventCreateWithFlags(&e, cudaEventDisableTiming); return e; }();
    static cudaEvent_t eBend = [] { cudaEvent_t e; cudaEventCreateWithFlags(&e, cudaEventDisableTiming); return e; }();

    cudaStream_t s0 = 0;   // default (capture) stream — chain A lives here

    // ---- fork: precompute on sPre, fold on s0, concurrently ----
    cudaEventRecord(eFork, s0);
    cudaStreamWaitEvent(sPre, eFork, 0);
    k_tbl<<<NFFT / 256, 256, 0, sPre>>>();
    k_pre<<<(N_CW + 255) / 256, 256, 0, sPre>>>(W, mag, ph);
    cudaEventRecord(ePre, sPre);

    k_fold<<<(BB * SH * (DD / 4)) / 256, 256, 0, s0>>>(x);

    // join precompute; then fork chain B
    cudaStreamWaitEvent(s0, ePre, 0);
    cudaEventRecord(eMid, s0);
    cudaStreamWaitEvent(sB, eMid, 0);

    // ---- two independent per-batch-half chains ----
    struct { cudaStream_t st; int b0; } chains[2] = { { s0, 0 }, { sB, HB } };
    for (int c = 0; c < 2; c++) {
        cudaStream_t st = chains[c].st;
        int b0 = chains[c].b0;

        // G1 (folded): X[b] = basis1f @ {xc|xd}[b], +x0 on cos tiles
        gemm_mma<3><<<dim3(DD / BN, K2 / BM, HB), 256, GEMM_SMEM, st>>>(
            (const __nv_bfloat16*)p_b1, SH,
            (const __nv_bfloat16*)p_xc, (const __nv_bfloat16*)p_xd, (size_t)SH * DD, DD,
            p_X, (size_t)K2 * DD, DD,
            x, (size_t)SS * DD,
            SH, /*bsel=*/2, b0);

        // elementwise complex weighting
        k_elem<<<(HB * KK * DD) / 256, 256, 0, st>>>(b0);

        // interference: deltar[b] = dpart + 0.1 * (WT @ xwr[b])
        gemm_mma<1><<<dim3(DD / BN, KK / BM, HB), 256, GEMM_SMEM, st>>>(
            (const __nv_bfloat16*)p_wt, KK,
            (const __nv_bfloat16*)p_xwr, (const __nv_bfloat16*)p_xwr, (size_t)KK * DD, DD,
            p_dl, (size_t)K2 * DD, DD,
            (const float*)p_dp, (size_t)KK * DD,
            KK, /*bsel=*/8, b0);

        // G2 (folded): ycs[b] (bf16) = basis2f @ {deltar|deltai}[b]
        gemm_mma<4><<<dim3(DD / BN, (2 * SH) / BM, HB), 256, GEMM_SMEM, st>>>(
            (const __nv_bfloat16*)p_b2, KK,
            (const __nv_bfloat16*)p_dl, (const __nv_bfloat16*)p_dl + (size_t)KK * DD,
            (size_t)K2 * DD, DD,
            p_ycs, (size_t)2 * SH * DD, DD,
            nullptr, 0,
            KK, /*bsel=*/8, b0);

        // combine: mirror + residual + row1024 + LayerNorm (fused dual-row reduction)
        k_combine<<<dim3(SH + 1, HB), 256, 0, st>>>(x, out, gamma, beta, b0);
    }

    // ---- join chain B back into the capture stream ----
    cudaEventRecord(eBend, sB);
    cudaStreamWaitEvent(s0, eBend, 0);
}

// round 16
// speedup vs baseline: 1.0329x; 1.0013x over previous
#include <cuda_runtime.h>
#include <cuda_bf16.h>
#include <cstdint>
#include <cstdio>

// Problem constants
#define BB   8
#define SS   2048
#define DD   1024
#define KK   256
#define NFFT 2048
#define K2   512
#define SH   1024   // folded length
#define HB   4      // batches per chain (2 chains)

// ---------------- device scratch ----------------
__device__ __align__(256) float2        g_tbl[NFFT];              // cos/sin table
__device__ __align__(256) __nv_bfloat16 g_basis1f[K2 * SH];       // rows 0..255 cos(f*s), 256..511 -sin(f*s); col = s-1
__device__ __align__(256) __nv_bfloat16 g_basis2f[2 * SH * KK];   // rows 0..1023 (c/N)cos, rows 1024..2047 -(c/N)sin
__device__ __align__(256) __nv_bfloat16 g_wt[KK * KK];            // WT[j][k] = W[k][j]
__device__ __align__(256) float         g_cwr[KK * DD];           // mag*cos(ph)
__device__ __align__(256) float         g_cwi[KK * DD];           // mag*sin(ph)
__device__ __align__(256) __nv_bfloat16 g_xc[BB * SH * DD];       // x_s + x_{2048-s}
__device__ __align__(256) __nv_bfloat16 g_xd[BB * SH * DD];       // x_s - x_{2048-s}
__device__ __align__(256) float         g_X[BB * K2 * DD];        // Xr rows 0..255, Xi rows 256..511
__device__ __align__(256) __nv_bfloat16 g_xwr[BB * KK * DD];      // Re(x_weighted)
__device__ __align__(256) __nv_bfloat16 g_delta[BB * K2 * DD];    // [deltar; deltai]
__device__ __align__(256) __nv_bfloat16 g_ycs[BB * 2 * SH * DD];  // bf16: rows 0..1023 ycos, 1024..2047 ysin

// ---------------- helpers ----------------
__device__ __forceinline__ int freq_of(int k) {
    if (k == 255) return 512;
    return (int)((double)k * (512.0 / 255.0));
}
__device__ __forceinline__ uint32_t smem_u32(const void* p) {
    return (uint32_t)__cvta_generic_to_shared(p);
}
__device__ __forceinline__ void cp_async16(void* smem_dst, const void* gmem_src) {
    asm volatile("cp.async.cg.shared.global [%0], [%1], 16;\n"
                 :: "r"(smem_u32(smem_dst)), "l"(gmem_src));
}
__device__ __forceinline__ void cp_commit() {
    asm volatile("cp.async.commit_group;\n");
}
template <int N>
__device__ __forceinline__ void cp_wait() {
    asm volatile("cp.async.wait_group %0;\n" :: "n"(N));
}

// ---------------- precompute ----------------
__global__ void k_tbl() {
    int m = blockIdx.x * blockDim.x + threadIdx.x;
    float ang = (float)m * (6.28318530717958647692f / (float)NFFT);
    float sv, cv;
    sincosf(ang, &sv, &cv);
    g_tbl[m] = make_float2(cv, sv);
}

// merged precompute: basis1f, basis2f, wt, cw
#define N_B1 (K2 * SH)
#define N_B2 (N_B1 + 2 * SH * KK)
#define N_WT (N_B2 + KK * KK)
#define N_CW (N_WT + KK * DD)
__global__ void k_pre(const float* __restrict__ W,
                      const float* __restrict__ mag, const float* __restrict__ ph) {
    int idx = blockIdx.x * blockDim.x + threadIdx.x;
    if (idx < N_B1) {
        int row = idx >> 10;             // 0..511
        int s   = (idx & 1023) + 1;      // 1..1024
        int f   = freq_of(row & 255);
        float2 t = g_tbl[(f * s) & (NFFT - 1)];
        g_basis1f[idx] = __float2bfloat16((row < KK) ? t.x : -t.y);
    } else if (idx < N_B2) {
        int i = idx - N_B1;
        int row = i >> 8;                // 0..2047
        int j   = i & 255;
        int s   = row & 1023;
        int f   = freq_of(j);
        float2 t = g_tbl[(f * s) & (NFFT - 1)];
        float scale = ((f == 0) ? 1.0f : 2.0f) * (1.0f / (float)NFFT);
        g_basis2f[i] = __float2bfloat16((row < SH) ? (scale * t.x) : (-scale * t.y));
    } else if (idx < N_WT) {
        int i = idx - N_B2;
        int j = i >> 8, k = i & 255;
        g_wt[i] = __float2bfloat16(W[k * KK + j]);
    } else if (idx < N_CW) {
        int i = idx - N_WT;
        float sp, cp;
        sincosf(ph[i], &sp, &cp);
        float m = mag[i];
        g_cwr[i] = m * cp;
        g_cwi[i] = m * sp;
    }
}

// ---------------- fold (all batches) ----------------
__global__ void k_fold(const float* __restrict__ x) {
    int idx = blockIdx.x * blockDim.x + threadIdx.x;
    if (idx >= BB * SH * (DD / 4)) return;
    int b   = idx >> 18;
    int r   = idx & 262143;
    int srow = r >> 8;
    int d4   = (r & 255) << 2;
    int s = srow + 1;
    const float* xb = x + (size_t)b * SS * DD;
    float4 xs = *(const float4*)(xb + (size_t)s * DD + d4);
    float4 c, d;
    if (s == 1024) {
        c = xs;
        d = make_float4(0.f, 0.f, 0.f, 0.f);
    } else {
        float4 xm = *(const float4*)(xb + (size_t)(SS - s) * DD + d4);
        c = make_float4(xs.x + xm.x, xs.y + xm.y, xs.z + xm.z, xs.w + xm.w);
        d = make_float4(xs.x - xm.x, xs.y - xm.y, xs.z - xm.z, xs.w - xm.w);
    }
    size_t o = ((size_t)b * SH + srow) * DD + d4;
    *(__nv_bfloat162*)&g_xc[o]     = __floats2bfloat162_rn(c.x, c.y);
    *(__nv_bfloat162*)&g_xc[o + 2] = __floats2bfloat162_rn(c.z, c.w);
    *(__nv_bfloat162*)&g_xd[o]     = __floats2bfloat162_rn(d.x, d.y);
    *(__nv_bfloat162*)&g_xd[o + 2] = __floats2bfloat162_rn(d.z, d.w);
}

// ---------------- elementwise complex weighting (HB batches, offset b0) ----------------
// writes xwr (bf16) and delta_i (bf16); dpart is reconstructed in the interf epilogue
__global__ void k_elem(int b0) {
    int idx = blockIdx.x * blockDim.x + threadIdx.x;
    if (idx >= HB * KK * DD) return;
    int b = (idx >> 18) + b0;
    int r = idx & 262143;   // k*1024 + d
    size_t xb = (size_t)b * (K2 * DD);
    size_t o1 = ((size_t)b << 18) + r;
    float Xr = g_X[xb + r];
    float Xi = g_X[xb + (KK * DD) + r];
    float cr = g_cwr[r];
    float ci = g_cwi[r];
    float xwr = Xr * cr - Xi * ci;
    float xwi = Xr * ci + Xi * cr;
    g_xwr[o1] = __float2bfloat16(xwr);
    g_delta[xb + (KK * DD) + r] = __float2bfloat16(xwi - Xi);
}

// ---------------- standard GEMM engine, 4-stage, batch-offset, templated BN ----------------
#define BM 128
#define BKg 32
#define NSTG 4
#define A_BYTES (BM * 40 * 2)
#define B_BYTES(BNt) (BKg * ((BNt) + 8) * 2)
#define GEMM_SMEM(BNt) (NSTG * (A_BYTES + B_BYTES(BNt)))

// MODE 1: bf16 store: (xwr - Xr) + 0.1*acc   (interference -> deltar; aux = g_X)
// MODE 3: fp32 store: acc (+ aux_row0[col] if aux && by<bsel)
// MODE 4: bf16 store: acc                    (G2 -> ycs)
template <int MODE, int BNt>
__global__ __launch_bounds__(256, 2) void gemm_mma(
    const __nv_bfloat16* __restrict__ A, int ldA,
    const __nv_bfloat16* __restrict__ B0, const __nv_bfloat16* __restrict__ B1,
    size_t sB, int ldB,
    void* __restrict__ Cv, size_t sC, int ldC,
    const float* __restrict__ aux, size_t sAux,
    int Kdim, int bsel, int b0)
{
    extern __shared__ __align__(16) char dsm[];

    constexpr int BSTRIDE = BNt + 8;        // elems
    constexpr int NI = BNt / 32;            // 8-col groups per warp
    constexpr int BCH = (BKg * BNt / 8) / 256;  // 16B chunks per thread for B

    int bz = blockIdx.z + b0;
    int bm = blockIdx.y * BM;
    int bn = blockIdx.x * BNt;
    const __nv_bfloat16* Ab = A;
    const __nv_bfloat16* Bb = ((int)blockIdx.y < bsel ? B0 : B1) + sB * bz;

    int tid = threadIdx.x, lane = tid & 31, warp = tid >> 5;
    int wm = (warp & 1) * 64;
    int wn = (warp >> 1) * (BNt / 4);

    int a_r0 = tid >> 2;
    int a_c  = (tid & 3) << 3;

    float acc[4][NI][4];
#pragma unroll
    for (int i = 0; i < 4; i++)
#pragma unroll
        for (int j = 0; j < NI; j++)
#pragma unroll
            for (int c = 0; c < 4; c++) acc[i][j][c] = 0.f;

    int nt = Kdim / BKg;

    auto a_base = [&](int st) -> char* { return dsm + st * A_BYTES; };
    auto b_base = [&](int st) -> char* { return dsm + NSTG * A_BYTES + st * B_BYTES(BNt); };

    auto load_stage = [&](int s) {
        char* ap = a_base(s & (NSTG - 1));
        char* bp = b_base(s & (NSTG - 1));
        int k0 = s * BKg;
        cp_async16(ap + (a_r0 * 40 + a_c) * 2,        Ab + (size_t)(bm + a_r0) * ldA + k0 + a_c);
        cp_async16(ap + ((a_r0 + 64) * 40 + a_c) * 2, Ab + (size_t)(bm + a_r0 + 64) * ldA + k0 + a_c);
#pragma unroll
        for (int j = 0; j < BCH; j++) {
            int chunk = tid + j * 256;
            int row = chunk / (BNt / 8);
            int col = (chunk % (BNt / 8)) << 3;
            cp_async16(bp + (row * BSTRIDE + col) * 2,
                       Bb + (size_t)(k0 + row) * ldB + bn + col);
        }
        cp_commit();
    };

#pragma unroll
    for (int i = 0; i < NSTG - 1; i++) load_stage(i);

    for (int kt = 0; kt < nt; kt++) {
        cp_wait<NSTG - 2>();
        __syncthreads();
        if (kt + NSTG - 1 < nt) load_stage(kt + NSTG - 1);
        else                    cp_commit();

        char* ap = a_base(kt & (NSTG - 1));
        char* bp = b_base(kt & (NSTG - 1));

#pragma unroll
        for (int kk = 0; kk < BKg; kk += 16) {
            uint32_t af[4][4], bf[NI][2];
            int ar = wm + (lane & 15);
            int ac = kk + ((lane >> 4) << 3);
#pragma unroll
            for (int mi = 0; mi < 4; mi++) {
                uint32_t ad = smem_u32(ap + ((ar + mi * 16) * 40 + ac) * 2);
                asm volatile("ldmatrix.sync.aligned.m8n8.x4.shared.b16 {%0,%1,%2,%3}, [%4];"
                             : "=r"(af[mi][0]), "=r"(af[mi][1]), "=r"(af[mi][2]), "=r"(af[mi][3])
                             : "r"(ad));
            }
            int br = kk + (lane & 15);
#pragma unroll
            for (int ni = 0; ni < NI; ni++) {
                uint32_t bd = smem_u32(bp + (br * BSTRIDE + wn + ni * 8) * 2);
                asm volatile("ldmatrix.sync.aligned.m8n8.x2.trans.shared.b16 {%0,%1}, [%2];"
                             : "=r"(bf[ni][0]), "=r"(bf[ni][1]) : "r"(bd));
            }
#pragma unroll
            for (int mi = 0; mi < 4; mi++)
#pragma unroll
                for (int ni = 0; ni < NI; ni++) {
                    float* d = acc[mi][ni];
                    asm volatile(
                        "mma.sync.aligned.m16n8k16.row.col.f32.bf16.bf16.f32 "
                        "{%0,%1,%2,%3}, {%4,%5,%6,%7}, {%8,%9}, {%0,%1,%2,%3};"
                        : "+f"(d[0]), "+f"(d[1]), "+f"(d[2]), "+f"(d[3])
                        : "r"(af[mi][0]), "r"(af[mi][1]), "r"(af[mi][2]), "r"(af[mi][3]),
                          "r"(bf[ni][0]), "r"(bf[ni][1]));
                }
        }
    }

    int g = lane >> 2, t2 = (lane & 3) << 1;
    bool addx = (MODE == 3) && (aux != nullptr) && ((int)blockIdx.y < bsel);
#pragma unroll
    for (int mi = 0; mi < 4; mi++) {
#pragma unroll
        for (int ni = 0; ni < NI; ni++) {
            int row0 = bm + wm + mi * 16 + g;
            int col  = bn + wn + ni * 8 + t2;
            float* d = acc[mi][ni];
            if (MODE == 3) {
                float* C = (float*)Cv + sC * bz;
                float ax0 = 0.f, ax1 = 0.f;
                if (addx) {
                    float2 a = *(const float2*)&aux[sAux * bz + col];
                    ax0 = a.x; ax1 = a.y;
                }
                *(float2*)&C[(size_t)row0 * ldC + col] =
                    make_float2(d[0] + ax0, d[1] + ax1);
                *(float2*)&C[(size_t)(row0 + 8) * ldC + col] =
                    make_float2(d[2] + ax0, d[3] + ax1);
            } else if (MODE == 4) {
                __nv_bfloat16* C = (__nv_bfloat16*)Cv + sC * bz;
                *(__nv_bfloat162*)&C[(size_t)row0 * ldC + col] =
                    __floats2bfloat162_rn(d[0], d[1]);
                *(__nv_bfloat162*)&C[(size_t)(row0 + 8) * ldC + col] =
                    __floats2bfloat162_rn(d[2], d[3]);
            } else {
                // MODE 1: deltar = (xwr - Xr) + 0.1*acc
                __nv_bfloat16* C = (__nv_bfloat16*)Cv + sC * bz;
                const float* Xb = aux + sAux * bz;
#pragma unroll
                for (int h = 0; h < 2; h++) {
                    int rr = row0 + h * 8;
                    __nv_bfloat162 xw = *(const __nv_bfloat162*)&Bb[(size_t)rr * ldB + col];
                    float2 Xr = *(const float2*)&Xb[(size_t)rr * ldC + col];
                    float v0 = (__bfloat162float(xw.x) - Xr.x) + 0.1f * d[2 * h];
                    float v1 = (__bfloat162float(xw.y) - Xr.y) + 0.1f * d[2 * h + 1];
                    *(__nv_bfloat162*)&C[(size_t)rr * ldC + col] =
                        __floats2bfloat162_rn(v0, v1);
                }
            }
        }
    }
}

// ---------------- combine (mirror + residual + row1024) + LayerNorm ----------------
__global__ __launch_bounds__(256) void k_combine(
    const float* __restrict__ x, float* __restrict__ out,
    const float* __restrict__ gamma, const float* __restrict__ beta, int b0)
{
    __shared__ float4 red[8];
    int b = blockIdx.y + b0, rp = blockIdx.x, t = threadIdx.x;
    int w = t >> 5, l = t & 31;
    int d4 = t << 2;
    const float* xb = x + (size_t)b * SS * DD;
    const __nv_bfloat16* ycs = g_ycs + (size_t)b * 2 * SH * DD;
    float4 gmv = ((const float4*)gamma)[t];
    float4 btv = ((const float4*)beta)[t];

    bool hasB = (rp >= 1 && rp < SH);
    float4 va, vb = make_float4(0.f, 0.f, 0.f, 0.f);

    if (rp < SH) {
        __nv_bfloat162 c0 = *(const __nv_bfloat162*)(ycs + (size_t)rp * DD + d4);
        __nv_bfloat162 c1 = *(const __nv_bfloat162*)(ycs + (size_t)rp * DD + d4 + 2);
        __nv_bfloat162 s0 = *(const __nv_bfloat162*)(ycs + (size_t)(SH + rp) * DD + d4);
        __nv_bfloat162 s1 = *(const __nv_bfloat162*)(ycs + (size_t)(SH + rp) * DD + d4 + 2);
        float vc0 = __bfloat162float(c0.x), vc1 = __bfloat162float(c0.y);
        float vc2 = __bfloat162float(c1.x), vc3 = __bfloat162float(c1.y);
        float vs0 = __bfloat162float(s0.x), vs1 = __bfloat162float(s0.y);
        float vs2 = __bfloat162float(s1.x), vs3 = __bfloat162float(s1.y);
        float4 xv = *(const float4*)(xb + (size_t)rp * DD + d4);
        va = make_float4(vc0 + vs0 + 2.f * xv.x, vc1 + vs1 + 2.f * xv.y,
                         vc2 + vs2 + 2.f * xv.z, vc3 + vs3 + 2.f * xv.w);
        if (hasB) {
            float4 xm = *(const float4*)(xb + (size_t)(SS - rp) * DD + d4);
            vb = make_float4(vc0 - vs0 + 2.f * xm.x, vc1 - vs1 + 2.f * xm.y,
                             vc2 - vs2 + 2.f * xm.z, vc3 - vs3 + 2.f * xm.w);
        }
    } else {
        float a0 = 0.f, a1 = 0.f, a2 = 0.f, a3 = 0.f;
        const __nv_bfloat16* dr = g_delta + (size_t)b * K2 * DD;
        for (int k = 0; k < KK; k++) {
            int f = freq_of(k);
            float wgt = ((f == 0) ? 1.0f : 2.0f) * (1.0f / (float)NFFT);
            if (f & 1) wgt = -wgt;
            __nv_bfloat162 p0 = *(const __nv_bfloat162*)(dr + (size_t)k * DD + d4);
            __nv_bfloat162 p1 = *(const __nv_bfloat162*)(dr + (size_t)k * DD + d4 + 2);
            a0 += wgt * __bfloat162float(p0.x);
            a1 += wgt * __bfloat162float(p0.y);
            a2 += wgt * __bfloat162float(p1.x);
            a3 += wgt * __bfloat162float(p1.y);
        }
        float4 xv = *(const float4*)(xb + (size_t)SH * DD + d4);
        va = make_float4(a0 + 2.f * xv.x, a1 + 2.f * xv.y,
                         a2 + 2.f * xv.z, a3 + 2.f * xv.w);
    }

    float s1a = va.x + va.y + va.z + va.w;
    float s2a = va.x * va.x + va.y * va.y + va.z * va.z + va.w * va.w;
    float s1b = vb.x + vb.y + vb.z + vb.w;
    float s2b = vb.x * vb.x + vb.y * vb.y + vb.z * vb.z + vb.w * vb.w;
#pragma unroll
    for (int o = 16; o > 0; o >>= 1) {
        s1a += __shfl_down_sync(0xffffffffu, s1a, o);
        s2a += __shfl_down_sync(0xffffffffu, s2a, o);
        s1b += __shfl_down_sync(0xffffffffu, s1b, o);
        s2b += __shfl_down_sync(0xffffffffu, s2b, o);
    }
    if (l == 0) red[w] = make_float4(s1a, s2a, s1b, s2b);
    __syncthreads();
    float muA = 0.f, m2A = 0.f, muB = 0.f, m2B = 0.f;
#pragma unroll
    for (int i = 0; i < 8; i++) {
        float4 rr = red[i];
        muA += rr.x; m2A += rr.y; muB += rr.z; m2B += rr.w;
    }
    muA *= (1.0f / (float)DD);
    float varA = m2A * (1.0f / (float)DD) - muA * muA;
    float rsA = rsqrtf(varA + 1e-5f);
    {
        float* op = out + ((size_t)b * SS + rp) * DD + d4;
        op[0] = (va.x - muA) * rsA * gmv.x + btv.x;
        op[1] = (va.y - muA) * rsA * gmv.y + btv.y;
        op[2] = (va.z - muA) * rsA * gmv.z + btv.z;
        op[3] = (va.w - muA) * rsA * gmv.w + btv.w;
    }
    if (hasB) {
        muB *= (1.0f / (float)DD);
        float varB = m2B * (1.0f / (float)DD) - muB * muB;
        float rsB = rsqrtf(varB + 1e-5f);
        float* op = out + ((size_t)b * SS + (SS - rp)) * DD + d4;
        op[0] = (vb.x - muB) * rsB * gmv.x + btv.x;
        op[1] = (vb.y - muB) * rsB * gmv.y + btv.y;
        op[2] = (vb.z - muB) * rsB * gmv.z + btv.z;
        op[3] = (vb.w - muB) * rsB * gmv.w + btv.w;
    }
}

// ---------------- launch (R11/R15 topology) ----------------
extern "C" void kernel_launch(void* const* d_in, const int* in_sizes, int n_in,
                              void* d_out, int out_size) {
    const float* x     = (const float*)d_in[0];
    const float* mag   = (const float*)d_in[1];
    const float* ph    = (const float*)d_in[2];
    const float* W     = (const float*)d_in[3];
    const float* gamma = (const float*)d_in[4];
    const float* beta  = (const float*)d_in[5];
    float* out = (float*)d_out;

    void *p_b1, *p_b2, *p_wt, *p_xc, *p_xd, *p_X, *p_xwr, *p_dl, *p_ycs;
    cudaGetSymbolAddress(&p_b1, g_basis1f);
    cudaGetSymbolAddress(&p_b2, g_basis2f);
    cudaGetSymbolAddress(&p_wt, g_wt);
    cudaGetSymbolAddress(&p_xc, g_xc);
    cudaGetSymbolAddress(&p_xd, g_xd);
    cudaGetSymbolAddress(&p_X, g_X);
    cudaGetSymbolAddress(&p_xwr, g_xwr);
    cudaGetSymbolAddress(&p_dl, g_delta);
    cudaGetSymbolAddress(&p_ycs, g_ycs);

    cudaFuncSetAttribute((const void*)gemm_mma<1, 64>,  cudaFuncAttributeMaxDynamicSharedMemorySize, GEMM_SMEM(64));
    cudaFuncSetAttribute((const void*)gemm_mma<3, 128>, cudaFuncAttributeMaxDynamicSharedMemorySize, GEMM_SMEM(128));
    cudaFuncSetAttribute((const void*)gemm_mma<4, 128>, cudaFuncAttributeMaxDynamicSharedMemorySize, GEMM_SMEM(128));

    static cudaStream_t sPre = [] { cudaStream_t s; cudaStreamCreateWithFlags(&s, cudaStreamNonBlocking); return s; }();
    static cudaStream_t sB   = [] { cudaStream_t s; cudaStreamCreateWithFlags(&s, cudaStreamNonBlocking); return s; }();
    static cudaEvent_t eFork = [] { cudaEvent_t e; cudaEventCreateWithFlags(&e, cudaEventDisableTiming); return e; }();
    static cudaEvent_t ePre  = [] { cudaEvent_t e; cudaEventCreateWithFlags(&e, cudaEventDisableTiming); return e; }();
    static cudaEvent_t eMid  = [] { cudaEvent_t e; cudaEventCreateWithFlags(&e, cudaEventDisableTiming); return e; }();
    static cudaEvent_t eBend = [] { cudaEvent_t e; cudaEventCreateWithFlags(&e, cudaEventDisableTiming); return e; }();

    cudaStream_t s0 = 0;   // default (capture) stream — chain A lives here

    // ---- fork: precompute on sPre, fold on s0, concurrently ----
    cudaEventRecord(eFork, s0);
    cudaStreamWaitEvent(sPre, eFork, 0);
    k_tbl<<<NFFT / 256, 256, 0, sPre>>>();
    k_pre<<<(N_CW + 255) / 256, 256, 0, sPre>>>(W, mag, ph);
    cudaEventRecord(ePre, sPre);

    k_fold<<<(BB * SH * (DD / 4)) / 256, 256, 0, s0>>>(x);

    cudaStreamWaitEvent(s0, ePre, 0);
    cudaEventRecord(eMid, s0);
    cudaStreamWaitEvent(sB, eMid, 0);

    // ---- two independent per-batch-half chains ----
    struct { cudaStream_t st; int b0; } chains[2] = { { s0, 0 }, { sB, HB } };
    for (int c = 0; c < 2; c++) {
        cudaStream_t st = chains[c].st;
        int b0 = chains[c].b0;

        // G1 (folded): X[b] = basis1f @ {xc|xd}[b], +x0 on cos tiles
        gemm_mma<3, 128><<<dim3(DD / 128, K2 / BM, HB), 256, GEMM_SMEM(128), st>>>(
            (const __nv_bfloat16*)p_b1, SH,
            (const __nv_bfloat16*)p_xc, (const __nv_bfloat16*)p_xd, (size_t)SH * DD, DD,
            p_X, (size_t)K2 * DD, DD,
            x, (size_t)SS * DD,
            SH, /*bsel=*/2, b0);

        // elementwise complex weighting
        k_elem<<<(HB * KK * DD) / 256, 256, 0, st>>>(b0);

        // interference: deltar[b] = (xwr - Xr) + 0.1 * (WT @ xwr[b])  [BN=64, better fill]
        gemm_mma<1, 64><<<dim3(DD / 64, KK / BM, HB), 256, GEMM_SMEM(64), st>>>(
            (const __nv_bfloat16*)p_wt, KK,
            (const __nv_bfloat16*)p_xwr, (const __nv_bfloat16*)p_xwr, (size_t)KK * DD, DD,
            p_dl, (size_t)K2 * DD, DD,
            (const float*)p_X, (size_t)K2 * DD,
            KK, /*bsel=*/8, b0);

        // G2 (folded): ycs[b] (bf16) = basis2f @ {deltar|deltai}[b]
        gemm_mma<4, 128><<<dim3(DD / 128, (2 * SH) / BM, HB), 256, GEMM_SMEM(128), st>>>(
            (const __nv_bfloat16*)p_b2, KK,
            (const __nv_bfloat16*)p_dl, (const __nv_bfloat16*)p_dl + (size_t)KK * DD,
            (size_t)K2 * DD, DD,
            p_ycs, (size_t)2 * SH * DD, DD,
            nullptr, 0,
            KK, /*bsel=*/8, b0);

        // combine: mirror + residual + row1024 + LayerNorm
        k_combine<<<dim3(SH + 1, HB), 256, 0, st>>>(x, out, gamma, beta, b0);
    }

    // ---- join chain B back into the capture stream ----
    cudaEventRecord(eBend, sB);
    cudaStreamWaitEvent(s0, eBend, 0);
}

// round 17
// speedup vs baseline: 1.0553x; 1.0216x over previous
#include <cuda_runtime.h>
#include <cuda_bf16.h>
#include <cstdint>
#include <cstdio>

// Problem constants
#define BB   8
#define SS   2048
#define DD   1024
#define KK   256
#define NFFT 2048
#define K2   512
#define SH   1024   // folded length
#define HB   4      // batches per chain (2 chains)

// ---------------- device scratch ----------------
__device__ __align__(256) float2        g_tbl[NFFT];              // cos/sin table
__device__ __align__(256) __nv_bfloat16 g_basis1f[K2 * SH];       // rows 0..255 cos(f*s), 256..511 -sin(f*s); col = s-1
__device__ __align__(256) __nv_bfloat16 g_basis2f[2 * SH * KK];   // rows 0..1023 (c/N)cos, rows 1024..2047 -(c/N)sin
__device__ __align__(256) __nv_bfloat16 g_wt[KK * KK];            // WT[j][k] = W[k][j]
__device__ __align__(256) float         g_cwr[KK * DD];           // mag*cos(ph)
__device__ __align__(256) float         g_cwi[KK * DD];           // mag*sin(ph)
__device__ __align__(256) __nv_bfloat16 g_xc[BB * SH * DD];       // x_s + x_{2048-s}
__device__ __align__(256) __nv_bfloat16 g_xd[BB * SH * DD];       // x_s - x_{2048-s}
__device__ __align__(256) float         g_X[BB * K2 * DD];        // Xr rows 0..255, Xi rows 256..511
__device__ __align__(256) __nv_bfloat16 g_xwr[BB * KK * DD];      // Re(x_weighted)
__device__ __align__(256) __nv_bfloat16 g_delta[BB * K2 * DD];    // [deltar; deltai]
__device__ __align__(256) __nv_bfloat16 g_ycs[BB * 2 * SH * DD];  // bf16: rows 0..1023 ycos, 1024..2047 ysin

// ---------------- helpers ----------------
__device__ __forceinline__ int freq_of(int k) {
    if (k == 255) return 512;
    return (int)((double)k * (512.0 / 255.0));
}
__device__ __forceinline__ uint32_t smem_u32(const void* p) {
    return (uint32_t)__cvta_generic_to_shared(p);
}
__device__ __forceinline__ void cp_async16(void* smem_dst, const void* gmem_src) {
    asm volatile("cp.async.cg.shared.global [%0], [%1], 16;\n"
                 :: "r"(smem_u32(smem_dst)), "l"(gmem_src));
}
__device__ __forceinline__ void cp_commit() {
    asm volatile("cp.async.commit_group;\n");
}
template <int N>
__device__ __forceinline__ void cp_wait() {
    asm volatile("cp.async.wait_group %0;\n" :: "n"(N));
}

// ---------------- precompute ----------------
__global__ void k_tbl() {
    int m = blockIdx.x * blockDim.x + threadIdx.x;
    float ang = (float)m * (6.28318530717958647692f / (float)NFFT);
    float sv, cv;
    sincosf(ang, &sv, &cv);
    g_tbl[m] = make_float2(cv, sv);
}

// merged precompute: basis1f, basis2f, wt, cw
#define N_B1 (K2 * SH)
#define N_B2 (N_B1 + 2 * SH * KK)
#define N_WT (N_B2 + KK * KK)
#define N_CW (N_WT + KK * DD)
__global__ void k_pre(const float* __restrict__ W,
                      const float* __restrict__ mag, const float* __restrict__ ph) {
    int idx = blockIdx.x * blockDim.x + threadIdx.x;
    if (idx < N_B1) {
        int row = idx >> 10;             // 0..511
        int s   = (idx & 1023) + 1;      // 1..1024
        int f   = freq_of(row & 255);
        float2 t = g_tbl[(f * s) & (NFFT - 1)];
        g_basis1f[idx] = __float2bfloat16((row < KK) ? t.x : -t.y);
    } else if (idx < N_B2) {
        int i = idx - N_B1;
        int row = i >> 8;                // 0..2047
        int j   = i & 255;
        int s   = row & 1023;
        int f   = freq_of(j);
        float2 t = g_tbl[(f * s) & (NFFT - 1)];
        float scale = ((f == 0) ? 1.0f : 2.0f) * (1.0f / (float)NFFT);
        g_basis2f[i] = __float2bfloat16((row < SH) ? (scale * t.x) : (-scale * t.y));
    } else if (idx < N_WT) {
        int i = idx - N_B2;
        int j = i >> 8, k = i & 255;
        g_wt[i] = __float2bfloat16(W[k * KK + j]);
    } else if (idx < N_CW) {
        int i = idx - N_WT;
        float sp, cp;
        sincosf(ph[i], &sp, &cp);
        float m = mag[i];
        g_cwr[i] = m * cp;
        g_cwi[i] = m * sp;
    }
}

// ---------------- fold (all batches) ----------------
__global__ void k_fold(const float* __restrict__ x) {
    int idx = blockIdx.x * blockDim.x + threadIdx.x;
    if (idx >= BB * SH * (DD / 4)) return;
    int b   = idx >> 18;
    int r   = idx & 262143;
    int srow = r >> 8;
    int d4   = (r & 255) << 2;
    int s = srow + 1;
    const float* xb = x + (size_t)b * SS * DD;
    float4 xs = *(const float4*)(xb + (size_t)s * DD + d4);
    float4 c, d;
    if (s == 1024) {
        c = xs;
        d = make_float4(0.f, 0.f, 0.f, 0.f);
    } else {
        float4 xm = *(const float4*)(xb + (size_t)(SS - s) * DD + d4);
        c = make_float4(xs.x + xm.x, xs.y + xm.y, xs.z + xm.z, xs.w + xm.w);
        d = make_float4(xs.x - xm.x, xs.y - xm.y, xs.z - xm.z, xs.w - xm.w);
    }
    size_t o = ((size_t)b * SH + srow) * DD + d4;
    *(__nv_bfloat162*)&g_xc[o]     = __floats2bfloat162_rn(c.x, c.y);
    *(__nv_bfloat162*)&g_xc[o + 2] = __floats2bfloat162_rn(c.z, c.w);
    *(__nv_bfloat162*)&g_xd[o]     = __floats2bfloat162_rn(d.x, d.y);
    *(__nv_bfloat162*)&g_xd[o + 2] = __floats2bfloat162_rn(d.z, d.w);
}

// ---------------- elementwise complex weighting (HB batches, offset b0) ----------------
__global__ void k_elem(int b0) {
    cudaGridDependencySynchronize();   // PDL: wait for producer (G1) before reading g_X
    int idx = blockIdx.x * blockDim.x + threadIdx.x;
    if (idx >= HB * KK * DD) return;
    int b = (idx >> 18) + b0;
    int r = idx & 262143;   // k*1024 + d
    size_t xb = (size_t)b * (K2 * DD);
    size_t o1 = ((size_t)b << 18) + r;
    float Xr = g_X[xb + r];
    float Xi = g_X[xb + (KK * DD) + r];
    float cr = g_cwr[r];
    float ci = g_cwi[r];
    float xwr = Xr * cr - Xi * ci;
    float xwi = Xr * ci + Xi * cr;
    g_xwr[o1] = __float2bfloat16(xwr);
    g_delta[xb + (KK * DD) + r] = __float2bfloat16(xwi - Xi);
}

// ---------------- standard GEMM engine, 4-stage, batch-offset, templated BN ----------------
#define BM 128
#define BKg 32
#define NSTG 4
#define A_BYTES (BM * 40 * 2)
#define B_BYTES(BNt) (BKg * ((BNt) + 8) * 2)
#define GEMM_SMEM(BNt) (NSTG * (A_BYTES + B_BYTES(BNt)))

// MODE 1: bf16 store: (xwr - Xr) + 0.1*acc   (interference -> deltar; aux = g_X)
// MODE 3: fp32 store: acc (+ aux_row0[col] if aux && by<bsel)
// MODE 4: bf16 store: acc                    (G2 -> ycs)
// PDL contract: the A operand must be independent of the in-stream producer
// (true: A = basis1f / wt / basis2f, all from k_pre which completed before the
// chain started). B/aux/epilogue reads happen after cudaGridDependencySynchronize().
template <int MODE, int BNt>
__global__ __launch_bounds__(256, 2) void gemm_mma(
    const __nv_bfloat16* __restrict__ A, int ldA,
    const __nv_bfloat16* __restrict__ B0, const __nv_bfloat16* __restrict__ B1,
    size_t sB, int ldB,
    void* __restrict__ Cv, size_t sC, int ldC,
    const float* __restrict__ aux, size_t sAux,
    int Kdim, int bsel, int b0)
{
    extern __shared__ __align__(16) char dsm[];

    constexpr int BSTRIDE = BNt + 8;        // elems
    constexpr int NI = BNt / 32;            // 8-col groups per warp
    constexpr int BCH = (BKg * BNt / 8) / 256;  // 16B chunks per thread for B

    int bz = blockIdx.z + b0;
    int bm = blockIdx.y * BM;
    int bn = blockIdx.x * BNt;
    const __nv_bfloat16* Ab = A;
    const __nv_bfloat16* Bb = ((int)blockIdx.y < bsel ? B0 : B1) + sB * bz;

    int tid = threadIdx.x, lane = tid & 31, warp = tid >> 5;
    int wm = (warp & 1) * 64;
    int wn = (warp >> 1) * (BNt / 4);

    int a_r0 = tid >> 2;
    int a_c  = (tid & 3) << 3;

    float acc[4][NI][4];
#pragma unroll
    for (int i = 0; i < 4; i++)
#pragma unroll
        for (int j = 0; j < NI; j++)
#pragma unroll
            for (int c = 0; c < 4; c++) acc[i][j][c] = 0.f;

    int nt = Kdim / BKg;

    auto a_base = [&](int st) -> char* { return dsm + st * A_BYTES; };
    auto b_base = [&](int st) -> char* { return dsm + NSTG * A_BYTES + st * B_BYTES(BNt); };

    auto load_A = [&](int s) {
        char* ap = a_base(s & (NSTG - 1));
        int k0 = s * BKg;
        cp_async16(ap + (a_r0 * 40 + a_c) * 2,        Ab + (size_t)(bm + a_r0) * ldA + k0 + a_c);
        cp_async16(ap + ((a_r0 + 64) * 40 + a_c) * 2, Ab + (size_t)(bm + a_r0 + 64) * ldA + k0 + a_c);
    };
    auto load_B = [&](int s) {
        char* bp = b_base(s & (NSTG - 1));
        int k0 = s * BKg;
#pragma unroll
        for (int j = 0; j < BCH; j++) {
            int chunk = tid + j * 256;
            int row = chunk / (BNt / 8);
            int col = (chunk % (BNt / 8)) << 3;
            cp_async16(bp + (row * BSTRIDE + col) * 2,
                       Bb + (size_t)(k0 + row) * ldB + bn + col);
        }
    };

    // PDL-aware prologue: prefetch ALL A stages (producer-independent), then wait
    // for the producer, then B stages. Group contents: g0={A0,A1,A2,B0}, g1={B1},
    // g2={B2} -> wait_group accounting in the main loop is unchanged.
#pragma unroll
    for (int i = 0; i < NSTG - 1; i++) load_A(i);
    cudaGridDependencySynchronize();
#pragma unroll
    for (int i = 0; i < NSTG - 1; i++) { load_B(i); cp_commit(); }

    for (int kt = 0; kt < nt; kt++) {
        cp_wait<NSTG - 2>();
        __syncthreads();
        if (kt + NSTG - 1 < nt) { load_A(kt + NSTG - 1); load_B(kt + NSTG - 1); cp_commit(); }
        else                    cp_commit();

        char* ap = a_base(kt & (NSTG - 1));
        char* bp = b_base(kt & (NSTG - 1));

#pragma unroll
        for (int kk = 0; kk < BKg; kk += 16) {
            uint32_t af[4][4], bf[NI][2];
            int ar = wm + (lane & 15);
            int ac = kk + ((lane >> 4) << 3);
#pragma unroll
            for (int mi = 0; mi < 4; mi++) {
                uint32_t ad = smem_u32(ap + ((ar + mi * 16) * 40 + ac) * 2);
                asm volatile("ldmatrix.sync.aligned.m8n8.x4.shared.b16 {%0,%1,%2,%3}, [%4];"
                             : "=r"(af[mi][0]), "=r"(af[mi][1]), "=r"(af[mi][2]), "=r"(af[mi][3])
                             : "r"(ad));
            }
            int br = kk + (lane & 15);
#pragma unroll
            for (int ni = 0; ni < NI; ni++) {
                uint32_t bd = smem_u32(bp + (br * BSTRIDE + wn + ni * 8) * 2);
                asm volatile("ldmatrix.sync.aligned.m8n8.x2.trans.shared.b16 {%0,%1}, [%2];"
                             : "=r"(bf[ni][0]), "=r"(bf[ni][1]) : "r"(bd));
            }
#pragma unroll
            for (int mi = 0; mi < 4; mi++)
#pragma unroll
                for (int ni = 0; ni < NI; ni++) {
                    float* d = acc[mi][ni];
                    asm volatile(
                        "mma.sync.aligned.m16n8k16.row.col.f32.bf16.bf16.f32 "
                        "{%0,%1,%2,%3}, {%4,%5,%6,%7}, {%8,%9}, {%0,%1,%2,%3};"
                        : "+f"(d[0]), "+f"(d[1]), "+f"(d[2]), "+f"(d[3])
                        : "r"(af[mi][0]), "r"(af[mi][1]), "r"(af[mi][2]), "r"(af[mi][3]),
                          "r"(bf[ni][0]), "r"(bf[ni][1]));
                }
        }
    }

    int g = lane >> 2, t2 = (lane & 3) << 1;
    bool addx = (MODE == 3) && (aux != nullptr) && ((int)blockIdx.y < bsel);
#pragma unroll
    for (int mi = 0; mi < 4; mi++) {
#pragma unroll
        for (int ni = 0; ni < NI; ni++) {
            int row0 = bm + wm + mi * 16 + g;
            int col  = bn + wn + ni * 8 + t2;
            float* d = acc[mi][ni];
            if (MODE == 3) {
                float* C = (float*)Cv + sC * bz;
                float ax0 = 0.f, ax1 = 0.f;
                if (addx) {
                    float2 a = *(const float2*)&aux[sAux * bz + col];
                    ax0 = a.x; ax1 = a.y;
                }
                *(float2*)&C[(size_t)row0 * ldC + col] =
                    make_float2(d[0] + ax0, d[1] + ax1);
                *(float2*)&C[(size_t)(row0 + 8) * ldC + col] =
                    make_float2(d[2] + ax0, d[3] + ax1);
            } else if (MODE == 4) {
                __nv_bfloat16* C = (__nv_bfloat16*)Cv + sC * bz;
                *(__nv_bfloat162*)&C[(size_t)row0 * ldC + col] =
                    __floats2bfloat162_rn(d[0], d[1]);
                *(__nv_bfloat162*)&C[(size_t)(row0 + 8) * ldC + col] =
                    __floats2bfloat162_rn(d[2], d[3]);
            } else {
                // MODE 1: deltar = (xwr - Xr) + 0.1*acc
                __nv_bfloat16* C = (__nv_bfloat16*)Cv + sC * bz;
                const float* Xb = aux + sAux * bz;
#pragma unroll
                for (int h = 0; h < 2; h++) {
                    int rr = row0 + h * 8;
                    __nv_bfloat162 xw = *(const __nv_bfloat162*)&Bb[(size_t)rr * ldB + col];
                    float2 Xr = *(const float2*)&Xb[(size_t)rr * ldC + col];
                    float v0 = (__bfloat162float(xw.x) - Xr.x) + 0.1f * d[2 * h];
                    float v1 = (__bfloat162float(xw.y) - Xr.y) + 0.1f * d[2 * h + 1];
                    *(__nv_bfloat162*)&C[(size_t)rr * ldC + col] =
                        __floats2bfloat162_rn(v0, v1);
                }
            }
        }
    }
}

// ---------------- combine (mirror + residual + row1024) + LayerNorm ----------------
__global__ __launch_bounds__(256) void k_combine(
    const float* __restrict__ x, float* __restrict__ out,
    const float* __restrict__ gamma, const float* __restrict__ beta, int b0)
{
    __shared__ float4 red[8];
    int b = blockIdx.y + b0, rp = blockIdx.x, t = threadIdx.x;
    int w = t >> 5, l = t & 31;
    int d4 = t << 2;
    const float* xb = x + (size_t)b * SS * DD;
    const __nv_bfloat16* ycs = g_ycs + (size_t)b * 2 * SH * DD;

    // producer-independent loads first (PDL overlap window)
    float4 gmv = ((const float4*)gamma)[t];
    float4 btv = ((const float4*)beta)[t];
    int rowA = (rp < SH) ? rp : SH;
    float4 xvA = *(const float4*)(xb + (size_t)rowA * DD + d4);

    cudaGridDependencySynchronize();   // PDL: wait for G2 before reading ycs/delta

    bool hasB = (rp >= 1 && rp < SH);
    float4 va, vb = make_float4(0.f, 0.f, 0.f, 0.f);

    if (rp < SH) {
        __nv_bfloat162 c0 = *(const __nv_bfloat162*)(ycs + (size_t)rp * DD + d4);
        __nv_bfloat162 c1 = *(const __nv_bfloat162*)(ycs + (size_t)rp * DD + d4 + 2);
        __nv_bfloat162 s0 = *(const __nv_bfloat162*)(ycs + (size_t)(SH + rp) * DD + d4);
        __nv_bfloat162 s1 = *(const __nv_bfloat162*)(ycs + (size_t)(SH + rp) * DD + d4 + 2);
        float vc0 = __bfloat162float(c0.x), vc1 = __bfloat162float(c0.y);
        float vc2 = __bfloat162float(c1.x), vc3 = __bfloat162float(c1.y);
        float vs0 = __bfloat162float(s0.x), vs1 = __bfloat162float(s0.y);
        float vs2 = __bfloat162float(s1.x), vs3 = __bfloat162float(s1.y);
        va = make_float4(vc0 + vs0 + 2.f * xvA.x, vc1 + vs1 + 2.f * xvA.y,
                         vc2 + vs2 + 2.f * xvA.z, vc3 + vs3 + 2.f * xvA.w);
        if (hasB) {
            float4 xm = *(const float4*)(xb + (size_t)(SS - rp) * DD + d4);
            vb = make_float4(vc0 - vs0 + 2.f * xm.x, vc1 - vs1 + 2.f * xm.y,
                             vc2 - vs2 + 2.f * xm.z, vc3 - vs3 + 2.f * xm.w);
        }
    } else {
        float a0 = 0.f, a1 = 0.f, a2 = 0.f, a3 = 0.f;
        const __nv_bfloat16* dr = g_delta + (size_t)b * K2 * DD;
        for (int k = 0; k < KK; k++) {
            int f = freq_of(k);
            float wgt = ((f == 0) ? 1.0f : 2.0f) * (1.0f / (float)NFFT);
            if (f & 1) wgt = -wgt;
            __nv_bfloat162 p0 = *(const __nv_bfloat162*)(dr + (size_t)k * DD + d4);
            __nv_bfloat162 p1 = *(const __nv_bfloat162*)(dr + (size_t)k * DD + d4 + 2);
            a0 += wgt * __bfloat162float(p0.x);
            a1 += wgt * __bfloat162float(p0.y);
            a2 += wgt * __bfloat162float(p1.x);
            a3 += wgt * __bfloat162float(p1.y);
        }
        va = make_float4(a0 + 2.f * xvA.x, a1 + 2.f * xvA.y,
                         a2 + 2.f * xvA.z, a3 + 2.f * xvA.w);
    }

    float s1a = va.x + va.y + va.z + va.w;
    float s2a = va.x * va.x + va.y * va.y + va.z * va.z + va.w * va.w;
    float s1b = vb.x + vb.y + vb.z + vb.w;
    float s2b = vb.x * vb.x + vb.y * vb.y + vb.z * vb.z + vb.w * vb.w;
#pragma unroll
    for (int o = 16; o > 0; o >>= 1) {
        s1a += __shfl_down_sync(0xffffffffu, s1a, o);
        s2a += __shfl_down_sync(0xffffffffu, s2a, o);
        s1b += __shfl_down_sync(0xffffffffu, s1b, o);
        s2b += __shfl_down_sync(0xffffffffu, s2b, o);
    }
    if (l == 0) red[w] = make_float4(s1a, s2a, s1b, s2b);
    __syncthreads();
    float muA = 0.f, m2A = 0.f, muB = 0.f, m2B = 0.f;
#pragma unroll
    for (int i = 0; i < 8; i++) {
        float4 rr = red[i];
        muA += rr.x; m2A += rr.y; muB += rr.z; m2B += rr.w;
    }
    muA *= (1.0f / (float)DD);
    float varA = m2A * (1.0f / (float)DD) - muA * muA;
    float rsA = rsqrtf(varA + 1e-5f);
    {
        float* op = out + ((size_t)b * SS + rp) * DD + d4;
        op[0] = (va.x - muA) * rsA * gmv.x + btv.x;
        op[1] = (va.y - muA) * rsA * gmv.y + btv.y;
        op[2] = (va.z - muA) * rsA * gmv.z + btv.z;
        op[3] = (va.w - muA) * rsA * gmv.w + btv.w;
    }
    if (hasB) {
        muB *= (1.0f / (float)DD);
        float varB = m2B * (1.0f / (float)DD) - muB * muB;
        float rsB = rsqrtf(varB + 1e-5f);
        float* op = out + ((size_t)b * SS + (SS - rp)) * DD + d4;
        op[0] = (vb.x - muB) * rsB * gmv.x + btv.x;
        op[1] = (vb.y - muB) * rsB * gmv.y + btv.y;
        op[2] = (vb.z - muB) * rsB * gmv.z + btv.z;
        op[3] = (vb.w - muB) * rsB * gmv.w + btv.w;
    }
}

// ---------------- PDL launch helper ----------------
template <typename F, typename... Args>
static inline void launch_pdl(F* kern, dim3 grid, dim3 block, size_t smem,
                              cudaStream_t st, Args... args) {
    cudaLaunchConfig_t cfg = {};
    cfg.gridDim = grid;
    cfg.blockDim = block;
    cfg.dynamicSmemBytes = smem;
    cfg.stream = st;
    cudaLaunchAttribute attr[1];
    attr[0].id = cudaLaunchAttributeProgrammaticStreamSerialization;
    attr[0].val.programmaticStreamSerializationAllowed = 1;
    cfg.attrs = attr;
    cfg.numAttrs = 1;
    cudaLaunchKernelEx(&cfg, kern, args...);
}

// ---------------- launch (R11/R15 topology + PDL on intra-chain edges) ----------------
extern "C" void kernel_launch(void* const* d_in, const int* in_sizes, int n_in,
                              void* d_out, int out_size) {
    const float* x     = (const float*)d_in[0];
    const float* mag   = (const float*)d_in[1];
    const float* ph    = (const float*)d_in[2];
    const float* W     = (const float*)d_in[3];
    const float* gamma = (const float*)d_in[4];
    const float* beta  = (const float*)d_in[5];
    float* out = (float*)d_out;

    void *p_b1, *p_b2, *p_wt, *p_xc, *p_xd, *p_X, *p_xwr, *p_dl, *p_ycs;
    cudaGetSymbolAddress(&p_b1, g_basis1f);
    cudaGetSymbolAddress(&p_b2, g_basis2f);
    cudaGetSymbolAddress(&p_wt, g_wt);
    cudaGetSymbolAddress(&p_xc, g_xc);
    cudaGetSymbolAddress(&p_xd, g_xd);
    cudaGetSymbolAddress(&p_X, g_X);
    cudaGetSymbolAddress(&p_xwr, g_xwr);
    cudaGetSymbolAddress(&p_dl, g_delta);
    cudaGetSymbolAddress(&p_ycs, g_ycs);

    cudaFuncSetAttribute((const void*)gemm_mma<1, 64>,  cudaFuncAttributeMaxDynamicSharedMemorySize, GEMM_SMEM(64));
    cudaFuncSetAttribute((const void*)gemm_mma<3, 128>, cudaFuncAttributeMaxDynamicSharedMemorySize, GEMM_SMEM(128));
    cudaFuncSetAttribute((const void*)gemm_mma<4, 128>, cudaFuncAttributeMaxDynamicSharedMemorySize, GEMM_SMEM(128));

    static cudaStream_t sPre = [] { cudaStream_t s; cudaStreamCreateWithFlags(&s, cudaStreamNonBlocking); return s; }();
    static cudaStream_t sB   = [] { cudaStream_t s; cudaStreamCreateWithFlags(&s, cudaStreamNonBlocking); return s; }();
    static cudaEvent_t eFork = [] { cudaEvent_t e; cudaEventCreateWithFlags(&e, cudaEventDisableTiming); return e; }();
    static cudaEvent_t ePre  = [] { cudaEvent_t e; cudaEventCreateWithFlags(&e, cudaEventDisableTiming); return e; }();
    static cudaEvent_t eMid  = [] { cudaEvent_t e; cudaEventCreateWithFlags(&e, cudaEventDisableTiming); return e; }();
    static cudaEvent_t eBend = [] { cudaEvent_t e; cudaEventCreateWithFlags(&e, cudaEventDisableTiming); return e; }();

    cudaStream_t s0 = 0;   // default (capture) stream — chain A lives here

    // ---- fork: precompute on sPre, fold on s0, concurrently ----
    cudaEventRecord(eFork, s0);
    cudaStreamWaitEvent(sPre, eFork, 0);
    k_tbl<<<NFFT / 256, 256, 0, sPre>>>();
    k_pre<<<(N_CW + 255) / 256, 256, 0, sPre>>>(W, mag, ph);
    cudaEventRecord(ePre, sPre);

    k_fold<<<(BB * SH * (DD / 4)) / 256, 256, 0, s0>>>(x);

    cudaStreamWaitEvent(s0, ePre, 0);
    cudaEventRecord(eMid, s0);
    cudaStreamWaitEvent(sB, eMid, 0);

    // ---- two independent per-batch-half chains (PDL on intra-chain edges) ----
    struct { cudaStream_t st; int b0; } chains[2] = { { s0, 0 }, { sB, HB } };
    for (int c = 0; c < 2; c++) {
        cudaStream_t st = chains[c].st;
        int b0 = chains[c].b0;

        // G1 (folded): normal launch (in-stream predecessor is an event wait)
        gemm_mma<3, 128><<<dim3(DD / 128, K2 / BM, HB), 256, GEMM_SMEM(128), st>>>(
            (const __nv_bfloat16*)p_b1, SH,
            (const __nv_bfloat16*)p_xc, (const __nv_bfloat16*)p_xd, (size_t)SH * DD, DD,
            p_X, (size_t)K2 * DD, DD,
            x, (size_t)SS * DD,
            SH, /*bsel=*/2, b0);

        // elementwise complex weighting (PDL over G1 tail)
        launch_pdl(k_elem, dim3((HB * KK * DD) / 256), dim3(256), 0, st, b0);

        // interference (PDL: wt-tile prefetch overlaps elem tail)
        launch_pdl(gemm_mma<1, 64>, dim3(DD / 64, KK / BM, HB), dim3(256), (size_t)GEMM_SMEM(64), st,
            (const __nv_bfloat16*)p_wt, (int)KK,
            (const __nv_bfloat16*)p_xwr, (const __nv_bfloat16*)p_xwr, (size_t)(KK * DD), (int)DD,
            (void*)p_dl, (size_t)(K2 * DD), (int)DD,
            (const float*)p_X, (size_t)(K2 * DD),
            (int)KK, 8, b0);

        // G2 (PDL: basis2f prefetch overlaps interference tail)
        launch_pdl(gemm_mma<4, 128>, dim3(DD / 128, (2 * SH) / BM, HB), dim3(256), (size_t)GEMM_SMEM(128), st,
            (const __nv_bfloat16*)p_b2, (int)KK,
            (const __nv_bfloat16*)p_dl, (const __nv_bfloat16*)(p_dl) + (size_t)KK * DD,
            (size_t)(K2 * DD), (int)DD,
            (void*)p_ycs, (size_t)(2 * SH * DD), (int)DD,
            (const float*)nullptr, (size_t)0,
            (int)KK, 8, b0);

        // combine (PDL: gamma/beta/x loads overlap G2 tail)
        launch_pdl(k_combine, dim3(SH + 1, HB), dim3(256), 0, st,
                   x, out, gamma, beta, b0);
    }

    // ---- join chain B back into the capture stream ----
    cudaEventRecord(eBend, sB);
    cudaStreamWaitEvent(s0, eBend, 0);
}